// round 8
// baseline (speedup 1.0000x reference)
#include <cuda_runtime.h>
#include <cuda_bf16.h>
#include <math.h>
#include <stdint.h>

#define DIMC   1024
#define HEADS  16
#define HD     64
#define MLPH   716
#define F1N    3788
#define F1NP   3840
#define QKVN   3072
#define MLPKP  768
#define ACLD   1792               /* AC = [xo(1024) | gelu(768)] */
#define BATCH  4
#define SEQ    1024
#define TOK    (BATCH*SEQ)
#define BH     (BATCH*HEADS)

typedef __nv_bfloat16 bf16;

/* ---------------- single scratch arena ------------------------------------- */
#define SZ_NORMX ((size_t)TOK*DIMC*2)
#define SZ_W1B   ((size_t)DIMC*F1NP*2)
#define SZ_PROJW ((size_t)DIMC*DIMC*2)
#define SZ_MLPW  ((size_t)MLPKP*DIMC*2)
#define SZ_W2B   ((size_t)2*DIMC*DIMC*2)
#define SZ_F1Q   ((size_t)TOK*QKVN*2)
#define SZ_AC    ((size_t)TOK*ACLD*2)
#define SZ_WF    ((size_t)ACLD*DIMC*2)
#define SZ_BF    ((size_t)DIMC*4)

#define OF_NORMX ((size_t)0)
#define OF_W1B   (OF_NORMX + SZ_NORMX)
#define OF_PROJW (OF_W1B   + SZ_W1B)
#define OF_MLPW  (OF_PROJW + SZ_PROJW)
#define OF_W2B   (OF_MLPW  + SZ_MLPW)
#define OF_F1Q   (OF_W2B   + SZ_W2B)
#define OF_AC    (OF_F1Q   + SZ_F1Q)
#define OF_WF    (OF_AC    + SZ_AC)
#define OF_BF    (OF_WF    + SZ_WF)
#define OF_END   (OF_BF    + SZ_BF)

__device__ __align__(256) unsigned char g_scratch[OF_END];

/* ---------------- PTX helpers ---------------------------------------------- */
__device__ __forceinline__ uint32_t smem_u32(const void* p) {
    return (uint32_t)__cvta_generic_to_shared(p);
}
__device__ __forceinline__ void cp16(uint32_t dst, const void* src) {
    asm volatile("cp.async.cg.shared.global [%0], [%1], 16;\n" :: "r"(dst), "l"(src));
}
__device__ __forceinline__ void cp_commit() { asm volatile("cp.async.commit_group;\n"); }
__device__ __forceinline__ void cp_wait0()  { asm volatile("cp.async.wait_group 0;\n"); }
__device__ __forceinline__ void cp_wait1()  { asm volatile("cp.async.wait_group 1;\n"); }
__device__ __forceinline__ void cp_wait2()  { asm volatile("cp.async.wait_group 2;\n"); }
__device__ __forceinline__ void ldm_x4(uint32_t& r0, uint32_t& r1, uint32_t& r2, uint32_t& r3, uint32_t a) {
    asm volatile("ldmatrix.sync.aligned.m8n8.x4.shared.b16 {%0,%1,%2,%3}, [%4];\n"
                 : "=r"(r0), "=r"(r1), "=r"(r2), "=r"(r3) : "r"(a));
}
__device__ __forceinline__ void ldm_x2(uint32_t& r0, uint32_t& r1, uint32_t a) {
    asm volatile("ldmatrix.sync.aligned.m8n8.x2.shared.b16 {%0,%1}, [%2];\n"
                 : "=r"(r0), "=r"(r1) : "r"(a));
}
__device__ __forceinline__ void ldm_x2_t(uint32_t& r0, uint32_t& r1, uint32_t a) {
    asm volatile("ldmatrix.sync.aligned.m8n8.x2.trans.shared.b16 {%0,%1}, [%2];\n"
                 : "=r"(r0), "=r"(r1) : "r"(a));
}
__device__ __forceinline__ void mma16816(float* c, const uint32_t* a, const uint32_t* b) {
    asm volatile("mma.sync.aligned.m16n8k16.row.col.f32.bf16.bf16.f32 "
                 "{%0,%1,%2,%3}, {%4,%5,%6,%7}, {%8,%9}, {%0,%1,%2,%3};\n"
                 : "+f"(c[0]), "+f"(c[1]), "+f"(c[2]), "+f"(c[3])
                 : "r"(a[0]), "r"(a[1]), "r"(a[2]), "r"(a[3]), "r"(b[0]), "r"(b[1]));
}
__device__ __forceinline__ uint32_t packbf2(float lo, float hi) {
    __nv_bfloat162 p = __floats2bfloat162_rn(lo, hi);
    return *(uint32_t*)&p;
}

/* ---------------- hgemm: 128x128x32 tiles, 3-stage cp.async (R4 core) ------
   A [M,K] row-major bf16, B [K,N] row-major bf16.
   EPI 1: bf16 C = acc + bias
   EPI 2: f32  C = resid + (acc+bias)*ls
   EPI 3: f1 dual: n<3072 -> bf16 Cv[m*3072+n]=acc+bias (f1 qkv)
                   n>=3072 -> bf16 C2v[m*ACLD+(n-3072)]=gelu(acc+bias)       */
#define HG_ASZ  (128*40)
#define HG_BSS  136
#define HG_BSZ  (32*HG_BSS)
#define HG_SMEM ((3*(HG_ASZ + HG_BSZ))*2)

__device__ __forceinline__ void hg_prefetch(
        const bf16* __restrict__ A, const bf16* __restrict__ B,
        bf16* As, bf16* Bs, int k0, int bm, int bn, int lda, int ldb, int t) {
    int ar = t >> 1, ac = (t & 1) * 16;
    uint32_t ad = smem_u32(As + ar * 40 + ac);
    const bf16* asrc = A + (size_t)(bm + ar) * lda + k0 + ac;
    cp16(ad, asrc);
    cp16(ad + 16, asrc + 8);
    int br = t >> 3, bc = (t & 7) * 16;
    uint32_t bd = smem_u32(Bs + br * HG_BSS + bc);
    const bf16* bsrc = B + (size_t)(k0 + br) * ldb + bn + bc;
    cp16(bd, bsrc);
    cp16(bd + 16, bsrc + 8);
}

template<int EPI>
__global__ __launch_bounds__(256) void hgemm(
        const bf16* __restrict__ A, const bf16* __restrict__ B,
        void* __restrict__ Cv, void* __restrict__ C2v,
        int K, int lda, int ldb, int ldc,
        const float* __restrict__ bias, int nbias,
        const float* __restrict__ resid, const float* __restrict__ ls) {
    extern __shared__ __align__(16) bf16 sm[];
    bf16* As = sm;
    bf16* Bs = sm + 3 * HG_ASZ;

    const int t = threadIdx.x;
    const int lane = t & 31, warp = t >> 5;
    const int bm = blockIdx.y * 128;
    const int bn = blockIdx.x * 128;
    const int wm = (warp >> 2) * 64;
    const int wn = (warp & 3) * 32;

    float acc[4][4][4];
    #pragma unroll
    for (int i = 0; i < 4; i++)
        #pragma unroll
        for (int j = 0; j < 4; j++)
            #pragma unroll
            for (int e = 0; e < 4; e++) acc[i][j][e] = 0.f;

    const int KT = K / 32;

    hg_prefetch(A, B, As, Bs, 0, bm, bn, lda, ldb, t);
    cp_commit();
    if (KT > 1) hg_prefetch(A, B, As + HG_ASZ, Bs + HG_BSZ, 32, bm, bn, lda, ldb, t);
    cp_commit();

    for (int kt = 0; kt < KT; kt++) {
        if (kt + 2 < KT) {
            int st = (kt + 2) % 3;
            hg_prefetch(A, B, As + st * HG_ASZ, Bs + st * HG_BSZ, (kt + 2) * 32, bm, bn, lda, ldb, t);
        }
        cp_commit();
        cp_wait2();
        __syncthreads();

        int s = kt % 3;
        bf16* as = As + s * HG_ASZ;
        bf16* bs = Bs + s * HG_BSZ;
        #pragma unroll
        for (int kk = 0; kk < 2; kk++) {
            uint32_t afr[4][4];
            #pragma unroll
            for (int i = 0; i < 4; i++) {
                uint32_t a = smem_u32(as + (wm + i * 16 + (lane & 15)) * 40 + kk * 16 + (lane >> 4) * 8);
                ldm_x4(afr[i][0], afr[i][1], afr[i][2], afr[i][3], a);
            }
            uint32_t bfr[4][2];
            #pragma unroll
            for (int j = 0; j < 4; j++) {
                uint32_t a = smem_u32(bs + (kk * 16 + (lane & 15)) * HG_BSS + wn + j * 8);
                ldm_x2_t(bfr[j][0], bfr[j][1], a);
            }
            #pragma unroll
            for (int i = 0; i < 4; i++)
                #pragma unroll
                for (int j = 0; j < 4; j++)
                    mma16816(acc[i][j], afr[i], bfr[j]);
        }
        __syncthreads();
    }

    #pragma unroll
    for (int i = 0; i < 4; i++) {
        int m0 = bm + wm + i * 16 + (lane >> 2);
        #pragma unroll
        for (int j = 0; j < 4; j++) {
            int n0 = bn + wn + j * 8 + (lane & 3) * 2;
            float b0 = 0.f, b1v = 0.f;
            if (bias != 0) {
                if (n0 < nbias)     b0  = bias[n0];
                if (n0 + 1 < nbias) b1v = bias[n0 + 1];
            }
            #pragma unroll
            for (int eh = 0; eh < 2; eh++) {
                int m = m0 + eh * 8;
                float v0 = acc[i][j][eh * 2 + 0] + b0;
                float v1 = acc[i][j][eh * 2 + 1] + b1v;
                if (EPI == 1) {
                    *(__nv_bfloat162*)((bf16*)Cv + (size_t)m * ldc + n0) =
                        __floats2bfloat162_rn(v0, v1);
                } else if (EPI == 2) {
                    const float2 r = *(const float2*)(resid + (size_t)m * ldc + n0);
                    float2 o;
                    o.x = r.x + v0 * ls[n0];
                    o.y = r.y + v1 * ls[n0 + 1];
                    *(float2*)((float*)Cv + (size_t)m * ldc + n0) = o;
                } else {  /* EPI 3 */
                    if (bn >= QKVN) {
                        float g0 = 0.5f * v0 * (1.f + erff(v0 * 0.70710678118654752f));
                        float g1 = 0.5f * v1 * (1.f + erff(v1 * 0.70710678118654752f));
                        *(__nv_bfloat162*)((bf16*)C2v + (size_t)m * ACLD + (n0 - QKVN)) =
                            __floats2bfloat162_rn(g0, g1);
                    } else {
                        *(__nv_bfloat162*)((bf16*)Cv + (size_t)m * QKVN + n0) =
                            __floats2bfloat162_rn(v0, v1);
                    }
                }
            }
        }
    }
}

/* ---------------- flash attention: reads q/k/v token-major from f1q --------- */
#define FA_LDS  72
#define FA_TSZ  (128*FA_LDS)
#define FA_SMEM ((5*FA_TSZ)*2)

__device__ __forceinline__ void fa_load_tile(const bf16* __restrict__ src, bf16* dst,
                                             int t, int ld) {
    #pragma unroll
    for (int i = 0; i < 4; i++) {
        int idx = t + i * 256;
        int r = idx >> 3, c = (idx & 7) * 8;
        cp16(smem_u32(dst + r * FA_LDS + c), src + (size_t)r * ld + c);
    }
}

__global__ __launch_bounds__(256, 1) void fattn(
        const bf16* __restrict__ f1q, bf16* __restrict__ ac) {
    extern __shared__ __align__(16) bf16 fsm[];
    bf16* Qs = fsm;
    bf16* Ks = fsm + FA_TSZ;
    bf16* Vs = fsm + 3 * FA_TSZ;

    const int t = threadIdx.x;
    const int lane = t & 31, w = t >> 5;
    const int bh = blockIdx.y;
    const int q0 = blockIdx.x * 128;
    const int b = bh / HEADS, h = bh % HEADS;
    const bf16* rowbase = f1q + (size_t)(b * SEQ) * QKVN;
    const bf16* qp = rowbase + (size_t)q0 * QKVN + h * HD;
    const bf16* kp = rowbase + DIMC + h * HD;
    const bf16* vp = rowbase + 2 * DIMC + h * HD;

    fa_load_tile(qp, Qs, t, QKVN);
    cp_commit();
    cp_wait0();
    __syncthreads();
    uint32_t qf[4][4];
    #pragma unroll
    for (int kk = 0; kk < 4; kk++) {
        uint32_t a = smem_u32(Qs + (w * 16 + (lane & 15)) * FA_LDS + kk * 16 + (lane >> 4) * 8);
        ldm_x4(qf[kk][0], qf[kk][1], qf[kk][2], qf[kk][3], a);
    }

    float oacc[8][4];
    #pragma unroll
    for (int jn = 0; jn < 8; jn++)
        #pragma unroll
        for (int e = 0; e < 4; e++) oacc[jn][e] = 0.f;
    float m0r = -1e30f, m1r = -1e30f, l0 = 0.f, l1 = 0.f;

    fa_load_tile(kp, Ks, t, QKVN);
    fa_load_tile(vp, Vs, t, QKVN);
    cp_commit();

    for (int c = 0; c < SEQ / 128; c++) {
        if (c + 1 < SEQ / 128) {
            int sn = (c + 1) & 1;
            fa_load_tile(kp + (size_t)(c + 1) * 128 * QKVN, Ks + sn * FA_TSZ, t, QKVN);
            fa_load_tile(vp + (size_t)(c + 1) * 128 * QKVN, Vs + sn * FA_TSZ, t, QKVN);
        }
        cp_commit();
        cp_wait1();
        __syncthreads();

        const int s = c & 1;
        bf16* ks = Ks + s * FA_TSZ;
        bf16* vs = Vs + s * FA_TSZ;

        float sacc[16][4];
        #pragma unroll
        for (int j = 0; j < 16; j++)
            #pragma unroll
            for (int e = 0; e < 4; e++) sacc[j][e] = 0.f;
        #pragma unroll
        for (int kk = 0; kk < 4; kk++) {
            #pragma unroll
            for (int j = 0; j < 16; j++) {
                uint32_t b0, b1;
                ldm_x2(b0, b1, smem_u32(ks + (j * 8 + (lane & 7)) * FA_LDS + kk * 16 + ((lane >> 3) & 1) * 8));
                uint32_t bb[2] = {b0, b1};
                mma16816(sacc[j], qf[kk], bb);
            }
        }
        #pragma unroll
        for (int j = 0; j < 16; j++)
            #pragma unroll
            for (int e = 0; e < 4; e++) sacc[j][e] *= 0.125f;

        float mx0 = -1e30f, mx1 = -1e30f;
        #pragma unroll
        for (int j = 0; j < 16; j++) {
            mx0 = fmaxf(mx0, fmaxf(sacc[j][0], sacc[j][1]));
            mx1 = fmaxf(mx1, fmaxf(sacc[j][2], sacc[j][3]));
        }
        mx0 = fmaxf(mx0, __shfl_xor_sync(0xffffffffu, mx0, 1));
        mx0 = fmaxf(mx0, __shfl_xor_sync(0xffffffffu, mx0, 2));
        mx1 = fmaxf(mx1, __shfl_xor_sync(0xffffffffu, mx1, 1));
        mx1 = fmaxf(mx1, __shfl_xor_sync(0xffffffffu, mx1, 2));
        float mn0 = fmaxf(m0r, mx0), mn1 = fmaxf(m1r, mx1);
        float al0 = __expf(m0r - mn0), al1 = __expf(m1r - mn1);
        m0r = mn0; m1r = mn1;

        float sum0 = 0.f, sum1 = 0.f;
        #pragma unroll
        for (int j = 0; j < 16; j++) {
            sacc[j][0] = __expf(sacc[j][0] - mn0);
            sacc[j][1] = __expf(sacc[j][1] - mn0);
            sacc[j][2] = __expf(sacc[j][2] - mn1);
            sacc[j][3] = __expf(sacc[j][3] - mn1);
            sum0 += sacc[j][0] + sacc[j][1];
            sum1 += sacc[j][2] + sacc[j][3];
        }
        sum0 += __shfl_xor_sync(0xffffffffu, sum0, 1);
        sum0 += __shfl_xor_sync(0xffffffffu, sum0, 2);
        sum1 += __shfl_xor_sync(0xffffffffu, sum1, 1);
        sum1 += __shfl_xor_sync(0xffffffffu, sum1, 2);
        l0 = l0 * al0 + sum0;
        l1 = l1 * al1 + sum1;
        #pragma unroll
        for (int jn = 0; jn < 8; jn++) {
            oacc[jn][0] *= al0; oacc[jn][1] *= al0;
            oacc[jn][2] *= al1; oacc[jn][3] *= al1;
        }

        uint32_t pa[8][4];
        #pragma unroll
        for (int jp = 0; jp < 8; jp++) {
            pa[jp][0] = packbf2(sacc[2 * jp][0],     sacc[2 * jp][1]);
            pa[jp][1] = packbf2(sacc[2 * jp][2],     sacc[2 * jp][3]);
            pa[jp][2] = packbf2(sacc[2 * jp + 1][0], sacc[2 * jp + 1][1]);
            pa[jp][3] = packbf2(sacc[2 * jp + 1][2], sacc[2 * jp + 1][3]);
        }
        #pragma unroll
        for (int jp = 0; jp < 8; jp++) {
            #pragma unroll
            for (int jn = 0; jn < 8; jn++) {
                uint32_t b0, b1;
                ldm_x2_t(b0, b1, smem_u32(vs + (jp * 16 + (lane & 15)) * FA_LDS + jn * 8));
                uint32_t bb[2] = {b0, b1};
                mma16816(oacc[jn], pa[jp], bb);
            }
        }
        __syncthreads();
    }

    /* epilogue: O /= l -> AC[:, 0:1024] token-major (ld = ACLD) */
    float inv0 = 1.f / l0, inv1 = 1.f / l1;
    int rA = lane >> 2;
    int tok0 = b * SEQ + q0 + w * 16 + rA;
    int colb = h * HD + (lane & 3) * 2;
    #pragma unroll
    for (int jn = 0; jn < 8; jn++) {
        __nv_bfloat162 v0 = __floats2bfloat162_rn(oacc[jn][0] * inv0, oacc[jn][1] * inv0);
        __nv_bfloat162 v1 = __floats2bfloat162_rn(oacc[jn][2] * inv1, oacc[jn][3] * inv1);
        *(__nv_bfloat162*)(ac + (size_t)tok0 * ACLD + colb + jn * 8) = v0;
        *(__nv_bfloat162*)(ac + (size_t)(tok0 + 8) * ACLD + colb + jn * 8) = v1;
    }
}

/* ---------------- reductions ------------------------------------------------ */
__device__ __forceinline__ float blockReduceSum(float val) {
    __shared__ float sh[32];
    int lane = threadIdx.x & 31, wid = threadIdx.x >> 5;
    #pragma unroll
    for (int o = 16; o > 0; o >>= 1) val += __shfl_down_sync(0xffffffffu, val, o);
    if (lane == 0) sh[wid] = val;
    __syncthreads();
    val = (threadIdx.x < (blockDim.x >> 5)) ? sh[threadIdx.x] : 0.f;
    if (wid == 0) {
        #pragma unroll
        for (int o = 16; o > 0; o >>= 1) val += __shfl_down_sync(0xffffffffu, val, o);
        if (lane == 0) sh[0] = val;
    }
    __syncthreads();
    float r = sh[0];
    __syncthreads();
    return r;
}

/* ---------------- LayerNorm -> bf16 ---------------------------------------- */
__global__ void ln_rows(const float* __restrict__ x, const float* __restrict__ g,
                        const float* __restrict__ b, bf16* __restrict__ outb) {
    int row = blockIdx.x, t = threadIdx.x;
    const float* xr = x + (size_t)row * DIMC;
    float v[4]; float s = 0.f;
    #pragma unroll
    for (int i = 0; i < 4; i++) { v[i] = xr[i * 256 + t]; s += v[i]; }
    float mean = blockReduceSum(s) * (1.f / DIMC);
    float s2 = 0.f;
    #pragma unroll
    for (int i = 0; i < 4; i++) { float d = v[i] - mean; s2 += d * d; }
    float inv = rsqrtf(blockReduceSum(s2) * (1.f / DIMC) + 1e-5f);
    bf16* orow = outb + (size_t)row * DIMC;
    #pragma unroll
    for (int i = 0; i < 4; i++) {
        int c = i * 256 + t;
        orow[c] = __float2bfloat16((v[i] - mean) * inv * g[c] + b[c]);
    }
}

/* ---------------- all four weight conversions in one launch ----------------- */
__global__ void convert_all(const float* __restrict__ W1, const float* __restrict__ projW,
                            const float* __restrict__ mlpW, const float* __restrict__ W2,
                            bf16* __restrict__ d1, bf16* __restrict__ d2,
                            bf16* __restrict__ d3, bf16* __restrict__ d4) {
    int z = blockIdx.y;
    const float* src; bf16* dst; int srows, scols, dcols; long long total;
    if (z == 0)      { src = W1;    dst = d1; srows = DIMC;   scols = F1N;  dcols = F1NP; total = (long long)DIMC * F1NP; }
    else if (z == 1) { src = projW; dst = d2; srows = DIMC;   scols = DIMC; dcols = DIMC; total = (long long)DIMC * DIMC; }
    else if (z == 2) { src = mlpW;  dst = d3; srows = MLPH;   scols = DIMC; dcols = DIMC; total = (long long)MLPKP * DIMC; }
    else             { src = W2;    dst = d4; srows = 2*DIMC; scols = DIMC; dcols = DIMC; total = (long long)2 * DIMC * DIMC; }
    long long i = (long long)blockIdx.x * 256 + threadIdx.x;
    if (i >= total) return;
    int r = (int)(i / dcols), c = (int)(i % dcols);
    float v = (r < srows && c < scols) ? src[(size_t)r * scols + c] : 0.f;
    dst[i] = __float2bfloat16(v);
}

/* ---------------- fused bias: biasf = projb @ W2[:1024] + b2 (fp32) --------- */
__global__ void bias_fuse(const float* __restrict__ projb, const float* __restrict__ W2,
                          const float* __restrict__ b2, float* __restrict__ bf) {
    int n = blockIdx.x * 256 + threadIdx.x;
    float s = b2[n];
    for (int k2 = 0; k2 < DIMC; k2++) s += projb[k2] * W2[(size_t)k2 * DIMC + n];
    bf[n] = s;
}

/* ---------------- in-place per-head LN on q,k inside f1q -------------------- */
__global__ void qkv_norm_inplace(bf16* __restrict__ f1,
                                 const float* __restrict__ qg, const float* __restrict__ qb,
                                 const float* __restrict__ kg, const float* __restrict__ kb) {
    int w = blockIdx.x * (blockDim.x >> 5) + (threadIdx.x >> 5);
    int lane = threadIdx.x & 31;
    int tkn = w >> 4, h = w & 15;
    bf16* row = f1 + (size_t)tkn * QKVN;
    int d0 = lane * 2, d1 = d0 + 1;
    {
        bf16* qp = row + h * HD;
        float v0 = __bfloat162float(qp[d0]);
        float v1 = __bfloat162float(qp[d1]);
        float s = v0 + v1;
        #pragma unroll
        for (int o = 16; o > 0; o >>= 1) s += __shfl_xor_sync(0xffffffffu, s, o);
        float m = s * (1.f / HD);
        float e0 = v0 - m, e1 = v1 - m;
        float s2 = e0 * e0 + e1 * e1;
        #pragma unroll
        for (int o = 16; o > 0; o >>= 1) s2 += __shfl_xor_sync(0xffffffffu, s2, o);
        float inv = rsqrtf(s2 * (1.f / HD) + 1e-5f);
        *(__nv_bfloat162*)(qp + d0) =
            __floats2bfloat162_rn(e0 * inv * qg[d0] + qb[d0], e1 * inv * qg[d1] + qb[d1]);
    }
    {
        bf16* kp = row + DIMC + h * HD;
        float v0 = __bfloat162float(kp[d0]);
        float v1 = __bfloat162float(kp[d1]);
        float s = v0 + v1;
        #pragma unroll
        for (int o = 16; o > 0; o >>= 1) s += __shfl_xor_sync(0xffffffffu, s, o);
        float m = s * (1.f / HD);
        float e0 = v0 - m, e1 = v1 - m;
        float s2 = e0 * e0 + e1 * e1;
        #pragma unroll
        for (int o = 16; o > 0; o >>= 1) s2 += __shfl_xor_sync(0xffffffffu, s2, o);
        float inv = rsqrtf(s2 * (1.f / HD) + 1e-5f);
        *(__nv_bfloat162*)(kp + d0) =
            __floats2bfloat162_rn(e0 * inv * kg[d0] + kb[d0], e1 * inv * kg[d1] + kb[d1]);
    }
}

/* ---------------- launcher -------------------------------------------------- */
extern "C" void kernel_launch(void* const* d_in, const int* in_sizes, int n_in,
                              void* d_out, int out_size) {
    const float* x      = (const float*)d_in[0];
    const float* norm_g = (const float*)d_in[1];
    const float* norm_b = (const float*)d_in[2];
    const float* W1     = (const float*)d_in[3];
    const float* b1     = (const float*)d_in[4];
    const float* qn_g   = (const float*)d_in[5];
    const float* qn_b   = (const float*)d_in[6];
    const float* kn_g   = (const float*)d_in[7];
    const float* kn_b   = (const float*)d_in[8];
    const float* projW  = (const float*)d_in[9];
    const float* projb  = (const float*)d_in[10];
    const float* mlpW   = (const float*)d_in[11];
    const float* W2     = (const float*)d_in[12];
    const float* b2     = (const float*)d_in[13];
    const float* ls_g   = (const float*)d_in[14];
    float* out = (float*)d_out;

    unsigned char* base = 0;
    cudaGetSymbolAddress((void**)&base, g_scratch);

    bf16*  p_normx = (bf16*)(base + OF_NORMX);
    bf16*  p_W1b   = (bf16*)(base + OF_W1B);
    bf16*  p_projWb= (bf16*)(base + OF_PROJW);
    bf16*  p_mlpWb = (bf16*)(base + OF_MLPW);
    bf16*  p_W2b   = (bf16*)(base + OF_W2B);
    bf16*  p_f1q   = (bf16*)(base + OF_F1Q);
    bf16*  p_ac    = (bf16*)(base + OF_AC);
    bf16*  p_wf    = (bf16*)(base + OF_WF);
    float* p_bf    = (float*)(base + OF_BF);

    static int attr_done = 0;
    if (!attr_done) {
        cudaFuncSetAttribute(hgemm<1>, cudaFuncAttributeMaxDynamicSharedMemorySize, HG_SMEM);
        cudaFuncSetAttribute(hgemm<2>, cudaFuncAttributeMaxDynamicSharedMemorySize, HG_SMEM);
        cudaFuncSetAttribute(hgemm<3>, cudaFuncAttributeMaxDynamicSharedMemorySize, HG_SMEM);
        cudaFuncSetAttribute(fattn,    cudaFuncAttributeMaxDynamicSharedMemorySize, FA_SMEM);
        attr_done = 1;
    }

    /* 0a. weight conversions (one launch) */
    convert_all<<<dim3((unsigned)(((long long)DIMC * F1NP + 255) / 256), 4), 256>>>(
        W1, projW, mlpW, W2, p_W1b, p_projWb, p_mlpWb, p_W2b);

    /* 0b. fused bias (fp32, exact) */
    bias_fuse<<<DIMC / 256, 256>>>(projb, W2, b2, p_bf);

    /* 0c. fused weights: Wf[0:1024]   = projW @ W2[0:1024]
                          Wf[1024:1792]= mlpW  @ W2[1024:2048] */
    hgemm<1><<<dim3(DIMC / 128, DIMC / 128), 256, HG_SMEM>>>(
        p_projWb, p_W2b, p_wf, 0, DIMC, DIMC, DIMC, DIMC, 0, 0, 0, 0);
    hgemm<1><<<dim3(DIMC / 128, MLPKP / 128), 256, HG_SMEM>>>(
        p_mlpWb, p_W2b + (size_t)DIMC * DIMC, p_wf + (size_t)DIMC * DIMC,
        0, DIMC, DIMC, DIMC, DIMC, 0, 0, 0, 0);

    /* 1. layernorm -> bf16 */
    ln_rows<<<TOK, 256>>>(x, norm_g, norm_b, p_normx);

    /* 2. f1 = normx @ W1 + b1 : qkv -> f1q bf16, gelu -> AC[:,1024:] bf16 */
    hgemm<3><<<dim3(F1NP / 128, TOK / 128), 256, HG_SMEM>>>(
        p_normx, p_W1b, p_f1q, p_ac + DIMC, DIMC, DIMC, F1NP, 0, b1, F1N, 0, 0);

    /* 3. per-head LN on q,k (in place) */
    qkv_norm_inplace<<<TOK * HEADS / 8, 256>>>(p_f1q, qn_g, qn_b, kn_g, kn_b);

    /* 4. flash attention -> AC[:, 0:1024] */
    fattn<<<dim3(SEQ / 128, BH), 256, FA_SMEM>>>(p_f1q, p_ac);

    /* 5. out = x + (AC @ Wf + biasf) * ls   [4096 x 1024 x 1792] */
    hgemm<2><<<dim3(DIMC / 128, TOK / 128), 256, HG_SMEM>>>(
        p_ac, p_wf, out, 0, ACLD, ACLD, DIMC, DIMC, p_bf, DIMC, x, ls_g);
}

// round 9
// speedup vs baseline: 1.0291x; 1.0291x over previous
#include <cuda_runtime.h>
#include <cuda_bf16.h>
#include <math.h>
#include <stdint.h>

#define DIMC   1024
#define HEADS  16
#define HD     64
#define MLPH   716
#define F1N    3788
#define F1NP   3840
#define QKVN   3072
#define MLPKP  768
#define BATCH  4
#define SEQ    1024
#define TOK    (BATCH*SEQ)
#define BH     (BATCH*HEADS)

typedef __nv_bfloat16 bf16;

/* ---------------- single scratch arena ------------------------------------- */
#define SZ_NORMX ((size_t)TOK*DIMC*2)
#define SZ_W1B   ((size_t)DIMC*F1NP*2)
#define SZ_PROJW ((size_t)DIMC*DIMC*2)
#define SZ_MLPW  ((size_t)MLPKP*DIMC*2)
#define SZ_W2B   ((size_t)2*DIMC*DIMC*2)
#define SZ_F1Q   ((size_t)TOK*QKVN*2)
#define SZ_XO    ((size_t)TOK*DIMC*2)
#define SZ_GELU  ((size_t)TOK*MLPKP*2)
#define SZ_COMB  ((size_t)TOK*2*DIMC*2)

#define OF_NORMX ((size_t)0)
#define OF_W1B   (OF_NORMX + SZ_NORMX)
#define OF_PROJW (OF_W1B   + SZ_W1B)
#define OF_MLPW  (OF_PROJW + SZ_PROJW)
#define OF_W2B   (OF_MLPW  + SZ_MLPW)
#define OF_F1Q   (OF_W2B   + SZ_W2B)
#define OF_XO    (OF_F1Q   + SZ_F1Q)
#define OF_GELU  (OF_XO    + SZ_XO)
#define OF_COMB  (OF_GELU  + SZ_GELU)
#define OF_END   (OF_COMB  + SZ_COMB)

__device__ __align__(256) unsigned char g_scratch[OF_END];

/* ---------------- PTX helpers ---------------------------------------------- */
__device__ __forceinline__ uint32_t smem_u32(const void* p) {
    return (uint32_t)__cvta_generic_to_shared(p);
}
__device__ __forceinline__ void cp16(uint32_t dst, const void* src) {
    asm volatile("cp.async.cg.shared.global [%0], [%1], 16;\n" :: "r"(dst), "l"(src));
}
__device__ __forceinline__ void cp_commit() { asm volatile("cp.async.commit_group;\n"); }
__device__ __forceinline__ void cp_wait0()  { asm volatile("cp.async.wait_group 0;\n"); }
__device__ __forceinline__ void cp_wait1()  { asm volatile("cp.async.wait_group 1;\n"); }
__device__ __forceinline__ void cp_wait2()  { asm volatile("cp.async.wait_group 2;\n"); }
__device__ __forceinline__ void ldm_x4(uint32_t& r0, uint32_t& r1, uint32_t& r2, uint32_t& r3, uint32_t a) {
    asm volatile("ldmatrix.sync.aligned.m8n8.x4.shared.b16 {%0,%1,%2,%3}, [%4];\n"
                 : "=r"(r0), "=r"(r1), "=r"(r2), "=r"(r3) : "r"(a));
}
__device__ __forceinline__ void ldm_x2(uint32_t& r0, uint32_t& r1, uint32_t a) {
    asm volatile("ldmatrix.sync.aligned.m8n8.x2.shared.b16 {%0,%1}, [%2];\n"
                 : "=r"(r0), "=r"(r1) : "r"(a));
}
__device__ __forceinline__ void ldm_x2_t(uint32_t& r0, uint32_t& r1, uint32_t a) {
    asm volatile("ldmatrix.sync.aligned.m8n8.x2.trans.shared.b16 {%0,%1}, [%2];\n"
                 : "=r"(r0), "=r"(r1) : "r"(a));
}
__device__ __forceinline__ void mma16816(float* c, const uint32_t* a, const uint32_t* b) {
    asm volatile("mma.sync.aligned.m16n8k16.row.col.f32.bf16.bf16.f32 "
                 "{%0,%1,%2,%3}, {%4,%5,%6,%7}, {%8,%9}, {%0,%1,%2,%3};\n"
                 : "+f"(c[0]), "+f"(c[1]), "+f"(c[2]), "+f"(c[3])
                 : "r"(a[0]), "r"(a[1]), "r"(a[2]), "r"(a[3]), "r"(b[0]), "r"(b[1]));
}
__device__ __forceinline__ uint32_t packbf2(float lo, float hi) {
    __nv_bfloat162 p = __floats2bfloat162_rn(lo, hi);
    return *(uint32_t*)&p;
}

/* ---------------- hgemm: 128x128x32 tiles, 3-stage cp.async ----------------
   A [M,K] row-major bf16, B [K,N] row-major bf16.
   EPI 1: bf16 C = acc + bias
   EPI 2: f32  C = resid + (acc+bias)*ls
   EPI 3: f1 dual: n<3072 -> bf16 Cv[m*3072+n]  n>=3072 -> C2v gelu          */
#define HG_ASZ  (128*40)
#define HG_BSS  136
#define HG_BSZ  (32*HG_BSS)
#define HG_SMEM ((3*(HG_ASZ + HG_BSZ))*2)

__device__ __forceinline__ void hg_prefetch(
        const bf16* __restrict__ A, const bf16* __restrict__ B,
        bf16* As, bf16* Bs, int k0, int bm, int bn, int lda, int ldb, int t) {
    int ar = t >> 1, ac = (t & 1) * 16;
    uint32_t ad = smem_u32(As + ar * 40 + ac);
    const bf16* asrc = A + (size_t)(bm + ar) * lda + k0 + ac;
    cp16(ad, asrc);
    cp16(ad + 16, asrc + 8);
    int br = t >> 3, bc = (t & 7) * 16;
    uint32_t bd = smem_u32(Bs + br * HG_BSS + bc);
    const bf16* bsrc = B + (size_t)(k0 + br) * ldb + bn + bc;
    cp16(bd, bsrc);
    cp16(bd + 16, bsrc + 8);
}

/* core compute: fills acc[4][4][4] over K (multiple of 32) */
__device__ __forceinline__ void hg_mainloop(
        const bf16* __restrict__ A, const bf16* __restrict__ B,
        bf16* As, bf16* Bs, float acc[4][4][4],
        int K, int lda, int ldb, int bm, int bn, int t, int lane, int wm, int wn) {
    const int KT = K / 32;
    hg_prefetch(A, B, As, Bs, 0, bm, bn, lda, ldb, t);
    cp_commit();
    if (KT > 1) hg_prefetch(A, B, As + HG_ASZ, Bs + HG_BSZ, 32, bm, bn, lda, ldb, t);
    cp_commit();

    for (int kt = 0; kt < KT; kt++) {
        if (kt + 2 < KT) {
            int st = (kt + 2) % 3;
            hg_prefetch(A, B, As + st * HG_ASZ, Bs + st * HG_BSZ, (kt + 2) * 32, bm, bn, lda, ldb, t);
        }
        cp_commit();
        cp_wait2();
        __syncthreads();

        int s = kt % 3;
        bf16* as = As + s * HG_ASZ;
        bf16* bs = Bs + s * HG_BSZ;
        #pragma unroll
        for (int kk = 0; kk < 2; kk++) {
            uint32_t afr[4][4];
            #pragma unroll
            for (int i = 0; i < 4; i++) {
                uint32_t a = smem_u32(as + (wm + i * 16 + (lane & 15)) * 40 + kk * 16 + (lane >> 4) * 8);
                ldm_x4(afr[i][0], afr[i][1], afr[i][2], afr[i][3], a);
            }
            uint32_t bfr[4][2];
            #pragma unroll
            for (int j = 0; j < 4; j++) {
                uint32_t a = smem_u32(bs + (kk * 16 + (lane & 15)) * HG_BSS + wn + j * 8);
                ldm_x2_t(bfr[j][0], bfr[j][1], a);
            }
            #pragma unroll
            for (int i = 0; i < 4; i++)
                #pragma unroll
                for (int j = 0; j < 4; j++)
                    mma16816(acc[i][j], afr[i], bfr[j]);
        }
        __syncthreads();
    }
}

template<int EPI>
__global__ __launch_bounds__(256) void hgemm(
        const bf16* __restrict__ A, const bf16* __restrict__ B,
        void* __restrict__ Cv, void* __restrict__ C2v,
        int K, int lda, int ldb, int ldc,
        const float* __restrict__ bias, int nbias,
        const float* __restrict__ resid, const float* __restrict__ ls) {
    extern __shared__ __align__(16) bf16 sm[];
    bf16* As = sm;
    bf16* Bs = sm + 3 * HG_ASZ;

    const int t = threadIdx.x;
    const int lane = t & 31, warp = t >> 5;
    const int bm = blockIdx.y * 128;
    const int bn = blockIdx.x * 128;
    const int wm = (warp >> 2) * 64;
    const int wn = (warp & 3) * 32;

    float acc[4][4][4];
    #pragma unroll
    for (int i = 0; i < 4; i++)
        #pragma unroll
        for (int j = 0; j < 4; j++)
            #pragma unroll
            for (int e = 0; e < 4; e++) acc[i][j][e] = 0.f;

    hg_mainloop(A, B, As, Bs, acc, K, lda, ldb, bm, bn, t, lane, wm, wn);

    #pragma unroll
    for (int i = 0; i < 4; i++) {
        int m0 = bm + wm + i * 16 + (lane >> 2);
        #pragma unroll
        for (int j = 0; j < 4; j++) {
            int n0 = bn + wn + j * 8 + (lane & 3) * 2;
            float b0 = 0.f, b1v = 0.f;
            if (bias != 0) {
                if (n0 < nbias)     b0  = bias[n0];
                if (n0 + 1 < nbias) b1v = bias[n0 + 1];
            }
            #pragma unroll
            for (int eh = 0; eh < 2; eh++) {
                int m = m0 + eh * 8;
                float v0 = acc[i][j][eh * 2 + 0] + b0;
                float v1 = acc[i][j][eh * 2 + 1] + b1v;
                if (EPI == 1) {
                    *(__nv_bfloat162*)((bf16*)Cv + (size_t)m * ldc + n0) =
                        __floats2bfloat162_rn(v0, v1);
                } else if (EPI == 2) {
                    const float2 r = *(const float2*)(resid + (size_t)m * ldc + n0);
                    float2 o;
                    o.x = r.x + v0 * ls[n0];
                    o.y = r.y + v1 * ls[n0 + 1];
                    *(float2*)((float*)Cv + (size_t)m * ldc + n0) = o;
                } else {  /* EPI 3 */
                    if (bn >= QKVN) {
                        float g0 = 0.5f * v0 * (1.f + erff(v0 * 0.70710678118654752f));
                        float g1 = 0.5f * v1 * (1.f + erff(v1 * 0.70710678118654752f));
                        *(__nv_bfloat162*)((bf16*)C2v + (size_t)m * MLPKP + (n0 - QKVN)) =
                            __floats2bfloat162_rn(g0, g1);
                    } else {
                        *(__nv_bfloat162*)((bf16*)Cv + (size_t)m * QKVN + n0) =
                            __floats2bfloat162_rn(v0, v1);
                    }
                }
            }
        }
    }
}

/* merged proj (z=0) + mlp (z=1) GEMM -> comb (ldc = 2048), bf16 out */
__global__ __launch_bounds__(256) void hgemm_pair(
        const bf16* __restrict__ A0, const bf16* __restrict__ B0,
        const bf16* __restrict__ A1, const bf16* __restrict__ B1,
        bf16* __restrict__ C, const float* __restrict__ bias0) {
    extern __shared__ __align__(16) bf16 sm[];
    bf16* As = sm;
    bf16* Bs = sm + 3 * HG_ASZ;

    const int t = threadIdx.x;
    const int lane = t & 31, warp = t >> 5;
    const int z = blockIdx.z;
    const bf16* A = z ? A1 : A0;
    const bf16* B = z ? B1 : B0;
    const int K = z ? MLPKP : DIMC;
    const float* bias = z ? (const float*)0 : bias0;
    const int bm = blockIdx.y * 128;
    const int bn = blockIdx.x * 128;
    const int wm = (warp >> 2) * 64;
    const int wn = (warp & 3) * 32;

    float acc[4][4][4];
    #pragma unroll
    for (int i = 0; i < 4; i++)
        #pragma unroll
        for (int j = 0; j < 4; j++)
            #pragma unroll
            for (int e = 0; e < 4; e++) acc[i][j][e] = 0.f;

    hg_mainloop(A, B, As, Bs, acc, K, K, DIMC, bm, bn, t, lane, wm, wn);

    const int nout = z * DIMC;
    #pragma unroll
    for (int i = 0; i < 4; i++) {
        int m0 = bm + wm + i * 16 + (lane >> 2);
        #pragma unroll
        for (int j = 0; j < 4; j++) {
            int n0 = bn + wn + j * 8 + (lane & 3) * 2;
            float b0 = bias ? bias[n0] : 0.f;
            float b1v = bias ? bias[n0 + 1] : 0.f;
            #pragma unroll
            for (int eh = 0; eh < 2; eh++) {
                int m = m0 + eh * 8;
                *(__nv_bfloat162*)(C + (size_t)m * (2 * DIMC) + nout + n0) =
                    __floats2bfloat162_rn(acc[i][j][eh * 2 + 0] + b0,
                                          acc[i][j][eh * 2 + 1] + b1v);
            }
        }
    }
}

/* ---------------- flash attention with fused q/k LayerNorm ------------------ */
#define FA_LDS  72
#define FA_TSZ  (128*FA_LDS)
#define FA_SMEM ((5*FA_TSZ)*2)

__device__ __forceinline__ void fa_load_tile(const bf16* __restrict__ src, bf16* dst,
                                             int t, int ld) {
    #pragma unroll
    for (int i = 0; i < 4; i++) {
        int idx = t + i * 256;
        int r = idx >> 3, c = (idx & 7) * 8;
        cp16(smem_u32(dst + r * FA_LDS + c), src + (size_t)r * ld + c);
    }
}

/* two-pass per-row LN over a 128x64 smem tile (2 threads per row) */
__device__ __forceinline__ void fa_ln_tile(bf16* tile, const float* g_s,
                                           const float* b_s, int t) {
    int r = t >> 1, h2 = t & 1;
    bf16* p = tile + r * FA_LDS + h2 * 32;
    float s = 0.f, s2 = 0.f;
    #pragma unroll
    for (int i = 0; i < 4; i++) {
        uint4 u = *(uint4*)(p + i * 8);
        const __nv_bfloat162* pr = (const __nv_bfloat162*)&u;
        #pragma unroll
        for (int j = 0; j < 4; j++) {
            float2 f2 = __bfloat1622float2(pr[j]);
            s += f2.x + f2.y;
            s2 += f2.x * f2.x + f2.y * f2.y;
        }
    }
    s  += __shfl_xor_sync(0xffffffffu, s, 1);
    s2 += __shfl_xor_sync(0xffffffffu, s2, 1);
    float m = s * (1.f / HD);
    float var = s2 * (1.f / HD) - m * m;
    float inv = rsqrtf(var + 1e-5f);
    int cb = h2 * 32;
    #pragma unroll
    for (int i = 0; i < 4; i++) {
        uint4 u = *(uint4*)(p + i * 8);
        __nv_bfloat162* pr = (__nv_bfloat162*)&u;
        #pragma unroll
        for (int j = 0; j < 4; j++) {
            float2 f2 = __bfloat1622float2(pr[j]);
            int c = cb + i * 8 + j * 2;
            pr[j] = __floats2bfloat162_rn((f2.x - m) * inv * g_s[c] + b_s[c],
                                          (f2.y - m) * inv * g_s[c + 1] + b_s[c + 1]);
        }
        *(uint4*)(p + i * 8) = u;
    }
}

__global__ __launch_bounds__(256, 1) void fattn(
        const bf16* __restrict__ f1q, bf16* __restrict__ xo,
        const float* __restrict__ qg, const float* __restrict__ qb,
        const float* __restrict__ kg, const float* __restrict__ kb) {
    extern __shared__ __align__(16) bf16 fsm[];
    bf16* Qs = fsm;
    bf16* Ks = fsm + FA_TSZ;
    bf16* Vs = fsm + 3 * FA_TSZ;
    __shared__ float qg_s[64], qb_s[64], kg_s[64], kb_s[64];

    const int t = threadIdx.x;
    const int lane = t & 31, w = t >> 5;
    const int bh = blockIdx.y;
    const int q0 = blockIdx.x * 128;
    const int b = bh / HEADS, h = bh % HEADS;
    const bf16* rowbase = f1q + (size_t)(b * SEQ) * QKVN;
    const bf16* qp = rowbase + (size_t)q0 * QKVN + h * HD;
    const bf16* kp = rowbase + DIMC + h * HD;
    const bf16* vp = rowbase + 2 * DIMC + h * HD;

    if (t < 64) {
        qg_s[t] = qg[t]; qb_s[t] = qb[t];
        kg_s[t] = kg[t]; kb_s[t] = kb[t];
    }

    fa_load_tile(qp, Qs, t, QKVN);
    cp_commit();
    /* start K/V chunk 0 early */
    fa_load_tile(kp, Ks, t, QKVN);
    fa_load_tile(vp, Vs, t, QKVN);
    cp_commit();

    cp_wait1();          /* Q group done */
    __syncthreads();
    fa_ln_tile(Qs, qg_s, qb_s, t);
    __syncthreads();
    uint32_t qf[4][4];
    #pragma unroll
    for (int kk = 0; kk < 4; kk++) {
        uint32_t a = smem_u32(Qs + (w * 16 + (lane & 15)) * FA_LDS + kk * 16 + (lane >> 4) * 8);
        ldm_x4(qf[kk][0], qf[kk][1], qf[kk][2], qf[kk][3], a);
    }

    float oacc[8][4];
    #pragma unroll
    for (int jn = 0; jn < 8; jn++)
        #pragma unroll
        for (int e = 0; e < 4; e++) oacc[jn][e] = 0.f;
    float m0r = -1e30f, m1r = -1e30f, l0 = 0.f, l1 = 0.f;

    for (int c = 0; c < SEQ / 128; c++) {
        if (c + 1 < SEQ / 128) {
            int sn = (c + 1) & 1;
            fa_load_tile(kp + (size_t)(c + 1) * 128 * QKVN, Ks + sn * FA_TSZ, t, QKVN);
            fa_load_tile(vp + (size_t)(c + 1) * 128 * QKVN, Vs + sn * FA_TSZ, t, QKVN);
        }
        cp_commit();
        cp_wait1();
        __syncthreads();

        const int s = c & 1;
        bf16* ks = Ks + s * FA_TSZ;
        bf16* vs = Vs + s * FA_TSZ;

        /* fused per-head LN on this K tile */
        fa_ln_tile(ks, kg_s, kb_s, t);
        __syncthreads();

        float sacc[16][4];
        #pragma unroll
        for (int j = 0; j < 16; j++)
            #pragma unroll
            for (int e = 0; e < 4; e++) sacc[j][e] = 0.f;
        #pragma unroll
        for (int kk = 0; kk < 4; kk++) {
            #pragma unroll
            for (int j = 0; j < 16; j++) {
                uint32_t b0, b1;
                ldm_x2(b0, b1, smem_u32(ks + (j * 8 + (lane & 7)) * FA_LDS + kk * 16 + ((lane >> 3) & 1) * 8));
                uint32_t bb[2] = {b0, b1};
                mma16816(sacc[j], qf[kk], bb);
            }
        }
        #pragma unroll
        for (int j = 0; j < 16; j++)
            #pragma unroll
            for (int e = 0; e < 4; e++) sacc[j][e] *= 0.125f;

        float mx0 = -1e30f, mx1 = -1e30f;
        #pragma unroll
        for (int j = 0; j < 16; j++) {
            mx0 = fmaxf(mx0, fmaxf(sacc[j][0], sacc[j][1]));
            mx1 = fmaxf(mx1, fmaxf(sacc[j][2], sacc[j][3]));
        }
        mx0 = fmaxf(mx0, __shfl_xor_sync(0xffffffffu, mx0, 1));
        mx0 = fmaxf(mx0, __shfl_xor_sync(0xffffffffu, mx0, 2));
        mx1 = fmaxf(mx1, __shfl_xor_sync(0xffffffffu, mx1, 1));
        mx1 = fmaxf(mx1, __shfl_xor_sync(0xffffffffu, mx1, 2));
        float mn0 = fmaxf(m0r, mx0), mn1 = fmaxf(m1r, mx1);
        float al0 = __expf(m0r - mn0), al1 = __expf(m1r - mn1);
        m0r = mn0; m1r = mn1;

        float sum0 = 0.f, sum1 = 0.f;
        #pragma unroll
        for (int j = 0; j < 16; j++) {
            sacc[j][0] = __expf(sacc[j][0] - mn0);
            sacc[j][1] = __expf(sacc[j][1] - mn0);
            sacc[j][2] = __expf(sacc[j][2] - mn1);
            sacc[j][3] = __expf(sacc[j][3] - mn1);
            sum0 += sacc[j][0] + sacc[j][1];
            sum1 += sacc[j][2] + sacc[j][3];
        }
        sum0 += __shfl_xor_sync(0xffffffffu, sum0, 1);
        sum0 += __shfl_xor_sync(0xffffffffu, sum0, 2);
        sum1 += __shfl_xor_sync(0xffffffffu, sum1, 1);
        sum1 += __shfl_xor_sync(0xffffffffu, sum1, 2);
        l0 = l0 * al0 + sum0;
        l1 = l1 * al1 + sum1;
        #pragma unroll
        for (int jn = 0; jn < 8; jn++) {
            oacc[jn][0] *= al0; oacc[jn][1] *= al0;
            oacc[jn][2] *= al1; oacc[jn][3] *= al1;
        }

        uint32_t pa[8][4];
        #pragma unroll
        for (int jp = 0; jp < 8; jp++) {
            pa[jp][0] = packbf2(sacc[2 * jp][0],     sacc[2 * jp][1]);
            pa[jp][1] = packbf2(sacc[2 * jp][2],     sacc[2 * jp][3]);
            pa[jp][2] = packbf2(sacc[2 * jp + 1][0], sacc[2 * jp + 1][1]);
            pa[jp][3] = packbf2(sacc[2 * jp + 1][2], sacc[2 * jp + 1][3]);
        }
        #pragma unroll
        for (int jp = 0; jp < 8; jp++) {
            #pragma unroll
            for (int jn = 0; jn < 8; jn++) {
                uint32_t b0, b1;
                ldm_x2_t(b0, b1, smem_u32(vs + (jp * 16 + (lane & 15)) * FA_LDS + jn * 8));
                uint32_t bb[2] = {b0, b1};
                mma16816(oacc[jn], pa[jp], bb);
            }
        }
        __syncthreads();
    }

    float inv0 = 1.f / l0, inv1 = 1.f / l1;
    int rA = lane >> 2;
    int tok0 = b * SEQ + q0 + w * 16 + rA;
    int colb = h * HD + (lane & 3) * 2;
    #pragma unroll
    for (int jn = 0; jn < 8; jn++) {
        __nv_bfloat162 v0 = __floats2bfloat162_rn(oacc[jn][0] * inv0, oacc[jn][1] * inv0);
        __nv_bfloat162 v1 = __floats2bfloat162_rn(oacc[jn][2] * inv1, oacc[jn][3] * inv1);
        *(__nv_bfloat162*)(xo + (size_t)tok0 * DIMC + colb + jn * 8) = v0;
        *(__nv_bfloat162*)(xo + (size_t)(tok0 + 8) * DIMC + colb + jn * 8) = v1;
    }
}

/* ---------------- reductions ------------------------------------------------ */
__device__ __forceinline__ float blockReduceSum(float val) {
    __shared__ float sh[32];
    int lane = threadIdx.x & 31, wid = threadIdx.x >> 5;
    #pragma unroll
    for (int o = 16; o > 0; o >>= 1) val += __shfl_down_sync(0xffffffffu, val, o);
    if (lane == 0) sh[wid] = val;
    __syncthreads();
    val = (threadIdx.x < (blockDim.x >> 5)) ? sh[threadIdx.x] : 0.f;
    if (wid == 0) {
        #pragma unroll
        for (int o = 16; o > 0; o >>= 1) val += __shfl_down_sync(0xffffffffu, val, o);
        if (lane == 0) sh[0] = val;
    }
    __syncthreads();
    float r = sh[0];
    __syncthreads();
    return r;
}

/* ---------------- LayerNorm -> bf16 ---------------------------------------- */
__global__ void ln_rows(const float* __restrict__ x, const float* __restrict__ g,
                        const float* __restrict__ b, bf16* __restrict__ outb) {
    int row = blockIdx.x, t = threadIdx.x;
    const float* xr = x + (size_t)row * DIMC;
    float v[4]; float s = 0.f;
    #pragma unroll
    for (int i = 0; i < 4; i++) { v[i] = xr[i * 256 + t]; s += v[i]; }
    float mean = blockReduceSum(s) * (1.f / DIMC);
    float s2 = 0.f;
    #pragma unroll
    for (int i = 0; i < 4; i++) { float d = v[i] - mean; s2 += d * d; }
    float inv = rsqrtf(blockReduceSum(s2) * (1.f / DIMC) + 1e-5f);
    bf16* orow = outb + (size_t)row * DIMC;
    #pragma unroll
    for (int i = 0; i < 4; i++) {
        int c = i * 256 + t;
        orow[c] = __float2bfloat16((v[i] - mean) * inv * g[c] + b[c]);
    }
}

/* ---------------- all four weight conversions in one launch ----------------- */
__global__ void convert_all(const float* __restrict__ W1, const float* __restrict__ projW,
                            const float* __restrict__ mlpW, const float* __restrict__ W2,
                            bf16* __restrict__ d1, bf16* __restrict__ d2,
                            bf16* __restrict__ d3, bf16* __restrict__ d4) {
    int z = blockIdx.y;
    const float* src; bf16* dst; int srows, scols, dcols; long long total;
    if (z == 0)      { src = W1;    dst = d1; srows = DIMC;   scols = F1N;  dcols = F1NP; total = (long long)DIMC * F1NP; }
    else if (z == 1) { src = projW; dst = d2; srows = DIMC;   scols = DIMC; dcols = DIMC; total = (long long)DIMC * DIMC; }
    else if (z == 2) { src = mlpW;  dst = d3; srows = MLPH;   scols = DIMC; dcols = DIMC; total = (long long)MLPKP * DIMC; }
    else             { src = W2;    dst = d4; srows = 2*DIMC; scols = DIMC; dcols = DIMC; total = (long long)2 * DIMC * DIMC; }
    long long i = (long long)blockIdx.x * 256 + threadIdx.x;
    if (i >= total) return;
    int r = (int)(i / dcols), c = (int)(i % dcols);
    float v = (r < srows && c < scols) ? src[(size_t)r * scols + c] : 0.f;
    dst[i] = __float2bfloat16(v);
}

/* ---------------- launcher -------------------------------------------------- */
extern "C" void kernel_launch(void* const* d_in, const int* in_sizes, int n_in,
                              void* d_out, int out_size) {
    const float* x      = (const float*)d_in[0];
    const float* norm_g = (const float*)d_in[1];
    const float* norm_b = (const float*)d_in[2];
    const float* W1     = (const float*)d_in[3];
    const float* b1     = (const float*)d_in[4];
    const float* qn_g   = (const float*)d_in[5];
    const float* qn_b   = (const float*)d_in[6];
    const float* kn_g   = (const float*)d_in[7];
    const float* kn_b   = (const float*)d_in[8];
    const float* projW  = (const float*)d_in[9];
    const float* projb  = (const float*)d_in[10];
    const float* mlpW   = (const float*)d_in[11];
    const float* W2     = (const float*)d_in[12];
    const float* b2     = (const float*)d_in[13];
    const float* ls_g   = (const float*)d_in[14];
    float* out = (float*)d_out;

    unsigned char* base = 0;
    cudaGetSymbolAddress((void**)&base, g_scratch);

    bf16*  p_normx = (bf16*)(base + OF_NORMX);
    bf16*  p_W1b   = (bf16*)(base + OF_W1B);
    bf16*  p_projWb= (bf16*)(base + OF_PROJW);
    bf16*  p_mlpWb = (bf16*)(base + OF_MLPW);
    bf16*  p_W2b   = (bf16*)(base + OF_W2B);
    bf16*  p_f1q   = (bf16*)(base + OF_F1Q);
    bf16*  p_xo    = (bf16*)(base + OF_XO);
    bf16*  p_gelu  = (bf16*)(base + OF_GELU);
    bf16*  p_comb  = (bf16*)(base + OF_COMB);

    static int attr_done = 0;
    if (!attr_done) {
        cudaFuncSetAttribute(hgemm<1>,  cudaFuncAttributeMaxDynamicSharedMemorySize, HG_SMEM);
        cudaFuncSetAttribute(hgemm<2>,  cudaFuncAttributeMaxDynamicSharedMemorySize, HG_SMEM);
        cudaFuncSetAttribute(hgemm<3>,  cudaFuncAttributeMaxDynamicSharedMemorySize, HG_SMEM);
        cudaFuncSetAttribute(hgemm_pair, cudaFuncAttributeMaxDynamicSharedMemorySize, HG_SMEM);
        cudaFuncSetAttribute(fattn,     cudaFuncAttributeMaxDynamicSharedMemorySize, FA_SMEM);
        attr_done = 1;
    }

    /* 0. weight conversions */
    convert_all<<<dim3((unsigned)(((long long)DIMC * F1NP + 255) / 256), 4), 256>>>(
        W1, projW, mlpW, W2, p_W1b, p_projWb, p_mlpWb, p_W2b);

    /* 1. layernorm -> bf16 */
    ln_rows<<<TOK, 256>>>(x, norm_g, norm_b, p_normx);

    /* 2. f1 = normx @ W1 + b1 : qkv -> f1q bf16, gelu -> p_gelu bf16 */
    hgemm<3><<<dim3(F1NP / 128, TOK / 128), 256, HG_SMEM>>>(
        p_normx, p_W1b, p_f1q, p_gelu, DIMC, DIMC, F1NP, 0, b1, F1N, 0, 0);

    /* 3. flash attention with fused q/k LN -> xo (token-major) */
    fattn<<<dim3(SEQ / 128, BH), 256, FA_SMEM>>>(p_f1q, p_xo, qn_g, qn_b, kn_g, kn_b);

    /* 4. merged proj + mlp -> comb */
    hgemm_pair<<<dim3(DIMC / 128, TOK / 128, 2), 256, HG_SMEM>>>(
        p_xo, p_projWb, p_gelu, p_mlpWb, p_comb, projb);

    /* 5. out = x + (comb @ W2 + b2) * ls_g  fp32 */
    hgemm<2><<<dim3(DIMC / 128, TOK / 128), 256, HG_SMEM>>>(
        p_comb, p_W2b, out, 0, 2 * DIMC, 2 * DIMC, DIMC, DIMC, b2, DIMC, x, ls_g);
}

// round 10
// speedup vs baseline: 1.0435x; 1.0140x over previous
#include <cuda_runtime.h>
#include <cuda_bf16.h>
#include <math.h>
#include <stdint.h>

#define DIMC   1024
#define HEADS  16
#define HD     64
#define MLPH   716
#define F1N    3788
#define F1NP   3840
#define QKVN   3072
#define MLPKP  768
#define BATCH  4
#define SEQ    1024
#define TOK    (BATCH*SEQ)
#define BH     (BATCH*HEADS)

typedef __nv_bfloat16 bf16;

/* ---------------- single scratch arena ------------------------------------- */
#define SZ_NORMX ((size_t)TOK*DIMC*2)
#define SZ_W1B   ((size_t)DIMC*F1NP*2)
#define SZ_PROJW ((size_t)DIMC*DIMC*2)
#define SZ_MLPW  ((size_t)MLPKP*DIMC*2)
#define SZ_W2B   ((size_t)2*DIMC*DIMC*2)
#define SZ_F1Q   ((size_t)TOK*QKVN*2)
#define SZ_XO    ((size_t)TOK*DIMC*2)
#define SZ_GELU  ((size_t)TOK*MLPKP*2)
#define SZ_COMB  ((size_t)TOK*2*DIMC*2)

#define OF_NORMX ((size_t)0)
#define OF_W1B   (OF_NORMX + SZ_NORMX)
#define OF_PROJW (OF_W1B   + SZ_W1B)
#define OF_MLPW  (OF_PROJW + SZ_PROJW)
#define OF_W2B   (OF_MLPW  + SZ_MLPW)
#define OF_F1Q   (OF_W2B   + SZ_W2B)
#define OF_XO    (OF_F1Q   + SZ_F1Q)
#define OF_GELU  (OF_XO    + SZ_XO)
#define OF_COMB  (OF_GELU  + SZ_GELU)
#define OF_END   (OF_COMB  + SZ_COMB)

__device__ __align__(256) unsigned char g_scratch[OF_END];

/* ---------------- PTX helpers ---------------------------------------------- */
__device__ __forceinline__ uint32_t smem_u32(const void* p) {
    return (uint32_t)__cvta_generic_to_shared(p);
}
__device__ __forceinline__ void cp16(uint32_t dst, const void* src) {
    asm volatile("cp.async.cg.shared.global [%0], [%1], 16;\n" :: "r"(dst), "l"(src));
}
__device__ __forceinline__ void cp_commit() { asm volatile("cp.async.commit_group;\n"); }
__device__ __forceinline__ void cp_wait0()  { asm volatile("cp.async.wait_group 0;\n"); }
__device__ __forceinline__ void cp_wait1()  { asm volatile("cp.async.wait_group 1;\n"); }
__device__ __forceinline__ void cp_wait2()  { asm volatile("cp.async.wait_group 2;\n"); }
__device__ __forceinline__ void ldm_x4(uint32_t& r0, uint32_t& r1, uint32_t& r2, uint32_t& r3, uint32_t a) {
    asm volatile("ldmatrix.sync.aligned.m8n8.x4.shared.b16 {%0,%1,%2,%3}, [%4];\n"
                 : "=r"(r0), "=r"(r1), "=r"(r2), "=r"(r3) : "r"(a));
}
__device__ __forceinline__ void ldm_x2(uint32_t& r0, uint32_t& r1, uint32_t a) {
    asm volatile("ldmatrix.sync.aligned.m8n8.x2.shared.b16 {%0,%1}, [%2];\n"
                 : "=r"(r0), "=r"(r1) : "r"(a));
}
__device__ __forceinline__ void ldm_x2_t(uint32_t& r0, uint32_t& r1, uint32_t a) {
    asm volatile("ldmatrix.sync.aligned.m8n8.x2.trans.shared.b16 {%0,%1}, [%2];\n"
                 : "=r"(r0), "=r"(r1) : "r"(a));
}
__device__ __forceinline__ void mma16816(float* c, const uint32_t* a, const uint32_t* b) {
    asm volatile("mma.sync.aligned.m16n8k16.row.col.f32.bf16.bf16.f32 "
                 "{%0,%1,%2,%3}, {%4,%5,%6,%7}, {%8,%9}, {%0,%1,%2,%3};\n"
                 : "+f"(c[0]), "+f"(c[1]), "+f"(c[2]), "+f"(c[3])
                 : "r"(a[0]), "r"(a[1]), "r"(a[2]), "r"(a[3]), "r"(b[0]), "r"(b[1]));
}
__device__ __forceinline__ uint32_t packbf2(float lo, float hi) {
    __nv_bfloat162 p = __floats2bfloat162_rn(lo, hi);
    return *(uint32_t*)&p;
}

/* ---------------- hgemm: 128x128x32 tiles, 3-stage cp.async ----------------
   A [M,K] row-major bf16, B [K,N] row-major bf16.
   EPI 1: bf16 C = acc + bias
   EPI 2: f32  C = resid + (acc+bias)*ls
   EPI 3: f1 dual: n<3072 -> bf16 Cv[m*3072+n]  n>=3072 -> C2v gelu          */
#define HG_ASZ  (128*40)
#define HG_BSS  136
#define HG_BSZ  (32*HG_BSS)
#define HG_SMEM ((3*(HG_ASZ + HG_BSZ))*2)

__device__ __forceinline__ void hg_prefetch(
        const bf16* __restrict__ A, const bf16* __restrict__ B,
        bf16* As, bf16* Bs, int k0, int bm, int bn, int lda, int ldb, int t) {
    int ar = t >> 1, ac = (t & 1) * 16;
    uint32_t ad = smem_u32(As + ar * 40 + ac);
    const bf16* asrc = A + (size_t)(bm + ar) * lda + k0 + ac;
    cp16(ad, asrc);
    cp16(ad + 16, asrc + 8);
    int br = t >> 3, bc = (t & 7) * 16;
    uint32_t bd = smem_u32(Bs + br * HG_BSS + bc);
    const bf16* bsrc = B + (size_t)(k0 + br) * ldb + bn + bc;
    cp16(bd, bsrc);
    cp16(bd + 16, bsrc + 8);
}

__device__ __forceinline__ void hg_mainloop(
        const bf16* __restrict__ A, const bf16* __restrict__ B,
        bf16* As, bf16* Bs, float acc[4][4][4],
        int K, int lda, int ldb, int bm, int bn, int t, int lane, int wm, int wn) {
    const int KT = K / 32;
    hg_prefetch(A, B, As, Bs, 0, bm, bn, lda, ldb, t);
    cp_commit();
    if (KT > 1) hg_prefetch(A, B, As + HG_ASZ, Bs + HG_BSZ, 32, bm, bn, lda, ldb, t);
    cp_commit();

    for (int kt = 0; kt < KT; kt++) {
        if (kt + 2 < KT) {
            int st = (kt + 2) % 3;
            hg_prefetch(A, B, As + st * HG_ASZ, Bs + st * HG_BSZ, (kt + 2) * 32, bm, bn, lda, ldb, t);
        }
        cp_commit();
        cp_wait2();
        __syncthreads();

        int s = kt % 3;
        bf16* as = As + s * HG_ASZ;
        bf16* bs = Bs + s * HG_BSZ;
        #pragma unroll
        for (int kk = 0; kk < 2; kk++) {
            uint32_t afr[4][4];
            #pragma unroll
            for (int i = 0; i < 4; i++) {
                uint32_t a = smem_u32(as + (wm + i * 16 + (lane & 15)) * 40 + kk * 16 + (lane >> 4) * 8);
                ldm_x4(afr[i][0], afr[i][1], afr[i][2], afr[i][3], a);
            }
            uint32_t bfr[4][2];
            #pragma unroll
            for (int j = 0; j < 4; j++) {
                uint32_t a = smem_u32(bs + (kk * 16 + (lane & 15)) * HG_BSS + wn + j * 8);
                ldm_x2_t(bfr[j][0], bfr[j][1], a);
            }
            #pragma unroll
            for (int i = 0; i < 4; i++)
                #pragma unroll
                for (int j = 0; j < 4; j++)
                    mma16816(acc[i][j], afr[i], bfr[j]);
        }
        __syncthreads();
    }
}

template<int EPI>
__global__ __launch_bounds__(256) void hgemm(
        const bf16* __restrict__ A, const bf16* __restrict__ B,
        void* __restrict__ Cv, void* __restrict__ C2v,
        int K, int lda, int ldb, int ldc,
        const float* __restrict__ bias, int nbias,
        const float* __restrict__ resid, const float* __restrict__ ls) {
    extern __shared__ __align__(16) bf16 sm[];
    bf16* As = sm;
    bf16* Bs = sm + 3 * HG_ASZ;

    const int t = threadIdx.x;
    const int lane = t & 31, warp = t >> 5;
    const int bm = blockIdx.y * 128;
    const int bn = blockIdx.x * 128;
    const int wm = (warp >> 2) * 64;
    const int wn = (warp & 3) * 32;

    float acc[4][4][4];
    #pragma unroll
    for (int i = 0; i < 4; i++)
        #pragma unroll
        for (int j = 0; j < 4; j++)
            #pragma unroll
            for (int e = 0; e < 4; e++) acc[i][j][e] = 0.f;

    hg_mainloop(A, B, As, Bs, acc, K, lda, ldb, bm, bn, t, lane, wm, wn);

    #pragma unroll
    for (int i = 0; i < 4; i++) {
        int m0 = bm + wm + i * 16 + (lane >> 2);
        #pragma unroll
        for (int j = 0; j < 4; j++) {
            int n0 = bn + wn + j * 8 + (lane & 3) * 2;
            float b0 = 0.f, b1v = 0.f;
            if (bias != 0) {
                if (n0 < nbias)     b0  = bias[n0];
                if (n0 + 1 < nbias) b1v = bias[n0 + 1];
            }
            #pragma unroll
            for (int eh = 0; eh < 2; eh++) {
                int m = m0 + eh * 8;
                float v0 = acc[i][j][eh * 2 + 0] + b0;
                float v1 = acc[i][j][eh * 2 + 1] + b1v;
                if (EPI == 1) {
                    *(__nv_bfloat162*)((bf16*)Cv + (size_t)m * ldc + n0) =
                        __floats2bfloat162_rn(v0, v1);
                } else if (EPI == 2) {
                    const float2 r = *(const float2*)(resid + (size_t)m * ldc + n0);
                    float2 o;
                    o.x = r.x + v0 * ls[n0];
                    o.y = r.y + v1 * ls[n0 + 1];
                    *(float2*)((float*)Cv + (size_t)m * ldc + n0) = o;
                } else {  /* EPI 3 */
                    if (bn >= QKVN) {
                        float g0 = 0.5f * v0 * (1.f + erff(v0 * 0.70710678118654752f));
                        float g1 = 0.5f * v1 * (1.f + erff(v1 * 0.70710678118654752f));
                        *(__nv_bfloat162*)((bf16*)C2v + (size_t)m * MLPKP + (n0 - QKVN)) =
                            __floats2bfloat162_rn(g0, g1);
                    } else {
                        *(__nv_bfloat162*)((bf16*)Cv + (size_t)m * QKVN + n0) =
                            __floats2bfloat162_rn(v0, v1);
                    }
                }
            }
        }
    }
}

/* merged proj (z=0) + mlp (z=1) GEMM -> comb (ldc = 2048), bf16 out */
__global__ __launch_bounds__(256) void hgemm_pair(
        const bf16* __restrict__ A0, const bf16* __restrict__ B0,
        const bf16* __restrict__ A1, const bf16* __restrict__ B1,
        bf16* __restrict__ C, const float* __restrict__ bias0) {
    extern __shared__ __align__(16) bf16 sm[];
    bf16* As = sm;
    bf16* Bs = sm + 3 * HG_ASZ;

    const int t = threadIdx.x;
    const int lane = t & 31, warp = t >> 5;
    const int z = blockIdx.z;
    const bf16* A = z ? A1 : A0;
    const bf16* B = z ? B1 : B0;
    const int K = z ? MLPKP : DIMC;
    const float* bias = z ? (const float*)0 : bias0;
    const int bm = blockIdx.y * 128;
    const int bn = blockIdx.x * 128;
    const int wm = (warp >> 2) * 64;
    const int wn = (warp & 3) * 32;

    float acc[4][4][4];
    #pragma unroll
    for (int i = 0; i < 4; i++)
        #pragma unroll
        for (int j = 0; j < 4; j++)
            #pragma unroll
            for (int e = 0; e < 4; e++) acc[i][j][e] = 0.f;

    hg_mainloop(A, B, As, Bs, acc, K, K, DIMC, bm, bn, t, lane, wm, wn);

    const int nout = z * DIMC;
    #pragma unroll
    for (int i = 0; i < 4; i++) {
        int m0 = bm + wm + i * 16 + (lane >> 2);
        #pragma unroll
        for (int j = 0; j < 4; j++) {
            int n0 = bn + wn + j * 8 + (lane & 3) * 2;
            float b0 = bias ? bias[n0] : 0.f;
            float b1v = bias ? bias[n0 + 1] : 0.f;
            #pragma unroll
            for (int eh = 0; eh < 2; eh++) {
                int m = m0 + eh * 8;
                *(__nv_bfloat162*)(C + (size_t)m * (2 * DIMC) + nout + n0) =
                    __floats2bfloat162_rn(acc[i][j][eh * 2 + 0] + b0,
                                          acc[i][j][eh * 2 + 1] + b1v);
            }
        }
    }
}

/* ---------------- flash attention, fused q/k LN, 64-key chunks -------------- */
#define FA_LDS  72
#define FA_TSZ  (128*FA_LDS)
#define FA_SMEM ((5*FA_TSZ)*2)

__device__ __forceinline__ void fa_load_tile(const bf16* __restrict__ src, bf16* dst,
                                             int t, int ld) {
    #pragma unroll
    for (int i = 0; i < 4; i++) {
        int idx = t + i * 256;
        int r = idx >> 3, c = (idx & 7) * 8;
        cp16(smem_u32(dst + r * FA_LDS + c), src + (size_t)r * ld + c);
    }
}

/* two-pass per-row LN over a 128x64 smem tile (2 threads per row) */
__device__ __forceinline__ void fa_ln_tile(bf16* tile, const float* g_s,
                                           const float* b_s, int t) {
    int r = t >> 1, h2 = t & 1;
    bf16* p = tile + r * FA_LDS + h2 * 32;
    float s = 0.f, s2 = 0.f;
    #pragma unroll
    for (int i = 0; i < 4; i++) {
        uint4 u = *(uint4*)(p + i * 8);
        const __nv_bfloat162* pr = (const __nv_bfloat162*)&u;
        #pragma unroll
        for (int j = 0; j < 4; j++) {
            float2 f2 = __bfloat1622float2(pr[j]);
            s += f2.x + f2.y;
            s2 += f2.x * f2.x + f2.y * f2.y;
        }
    }
    s  += __shfl_xor_sync(0xffffffffu, s, 1);
    s2 += __shfl_xor_sync(0xffffffffu, s2, 1);
    float m = s * (1.f / HD);
    float var = s2 * (1.f / HD) - m * m;
    float inv = rsqrtf(var + 1e-5f);
    int cb = h2 * 32;
    #pragma unroll
    for (int i = 0; i < 4; i++) {
        uint4 u = *(uint4*)(p + i * 8);
        __nv_bfloat162* pr = (__nv_bfloat162*)&u;
        #pragma unroll
        for (int j = 0; j < 4; j++) {
            float2 f2 = __bfloat1622float2(pr[j]);
            int c = cb + i * 8 + j * 2;
            pr[j] = __floats2bfloat162_rn((f2.x - m) * inv * g_s[c] + b_s[c],
                                          (f2.y - m) * inv * g_s[c + 1] + b_s[c + 1]);
        }
        *(uint4*)(p + i * 8) = u;
    }
}

__global__ __launch_bounds__(256, 2) void fattn(
        const bf16* __restrict__ f1q, bf16* __restrict__ xo,
        const float* __restrict__ qg, const float* __restrict__ qb,
        const float* __restrict__ kg, const float* __restrict__ kb) {
    extern __shared__ __align__(16) bf16 fsm[];
    bf16* Qs = fsm;
    bf16* Ks = fsm + FA_TSZ;
    bf16* Vs = fsm + 3 * FA_TSZ;
    __shared__ float qg_s[64], qb_s[64], kg_s[64], kb_s[64];

    const int t = threadIdx.x;
    const int lane = t & 31, w = t >> 5;
    const int bh = blockIdx.y;
    const int q0 = blockIdx.x * 128;
    const int b = bh / HEADS, h = bh % HEADS;
    const bf16* rowbase = f1q + (size_t)(b * SEQ) * QKVN;
    const bf16* qp = rowbase + (size_t)q0 * QKVN + h * HD;
    const bf16* kp = rowbase + DIMC + h * HD;
    const bf16* vp = rowbase + 2 * DIMC + h * HD;

    if (t < 64) {
        qg_s[t] = qg[t]; qb_s[t] = qb[t];
        kg_s[t] = kg[t]; kb_s[t] = kb[t];
    }

    fa_load_tile(qp, Qs, t, QKVN);
    cp_commit();
    fa_load_tile(kp, Ks, t, QKVN);
    fa_load_tile(vp, Vs, t, QKVN);
    cp_commit();

    cp_wait1();
    __syncthreads();
    fa_ln_tile(Qs, qg_s, qb_s, t);
    __syncthreads();
    uint32_t qf[4][4];
    #pragma unroll
    for (int kk = 0; kk < 4; kk++) {
        uint32_t a = smem_u32(Qs + (w * 16 + (lane & 15)) * FA_LDS + kk * 16 + (lane >> 4) * 8);
        ldm_x4(qf[kk][0], qf[kk][1], qf[kk][2], qf[kk][3], a);
    }

    float oacc[8][4];
    #pragma unroll
    for (int jn = 0; jn < 8; jn++)
        #pragma unroll
        for (int e = 0; e < 4; e++) oacc[jn][e] = 0.f;
    float m0r = -1e30f, m1r = -1e30f, l0 = 0.f, l1 = 0.f;

    for (int c = 0; c < SEQ / 128; c++) {
        if (c + 1 < SEQ / 128) {
            int sn = (c + 1) & 1;
            fa_load_tile(kp + (size_t)(c + 1) * 128 * QKVN, Ks + sn * FA_TSZ, t, QKVN);
            fa_load_tile(vp + (size_t)(c + 1) * 128 * QKVN, Vs + sn * FA_TSZ, t, QKVN);
        }
        cp_commit();
        cp_wait1();
        __syncthreads();

        const int s = c & 1;
        bf16* ks = Ks + s * FA_TSZ;
        bf16* vs = Vs + s * FA_TSZ;

        fa_ln_tile(ks, kg_s, kb_s, t);
        __syncthreads();

        /* two 64-key halves: smaller live register set */
        #pragma unroll
        for (int half = 0; half < 2; half++) {
            bf16* ksh = ks + half * 64 * FA_LDS;
            bf16* vsh = vs + half * 64 * FA_LDS;

            float sacc[8][4];
            #pragma unroll
            for (int j = 0; j < 8; j++)
                #pragma unroll
                for (int e = 0; e < 4; e++) sacc[j][e] = 0.f;
            #pragma unroll
            for (int kk = 0; kk < 4; kk++) {
                #pragma unroll
                for (int j = 0; j < 8; j++) {
                    uint32_t b0, b1;
                    ldm_x2(b0, b1, smem_u32(ksh + (j * 8 + (lane & 7)) * FA_LDS + kk * 16 + ((lane >> 3) & 1) * 8));
                    uint32_t bb[2] = {b0, b1};
                    mma16816(sacc[j], qf[kk], bb);
                }
            }
            #pragma unroll
            for (int j = 0; j < 8; j++)
                #pragma unroll
                for (int e = 0; e < 4; e++) sacc[j][e] *= 0.125f;

            float mx0 = -1e30f, mx1 = -1e30f;
            #pragma unroll
            for (int j = 0; j < 8; j++) {
                mx0 = fmaxf(mx0, fmaxf(sacc[j][0], sacc[j][1]));
                mx1 = fmaxf(mx1, fmaxf(sacc[j][2], sacc[j][3]));
            }
            mx0 = fmaxf(mx0, __shfl_xor_sync(0xffffffffu, mx0, 1));
            mx0 = fmaxf(mx0, __shfl_xor_sync(0xffffffffu, mx0, 2));
            mx1 = fmaxf(mx1, __shfl_xor_sync(0xffffffffu, mx1, 1));
            mx1 = fmaxf(mx1, __shfl_xor_sync(0xffffffffu, mx1, 2));
            float mn0 = fmaxf(m0r, mx0), mn1 = fmaxf(m1r, mx1);
            float al0 = __expf(m0r - mn0), al1 = __expf(m1r - mn1);
            m0r = mn0; m1r = mn1;

            float sum0 = 0.f, sum1 = 0.f;
            #pragma unroll
            for (int j = 0; j < 8; j++) {
                sacc[j][0] = __expf(sacc[j][0] - mn0);
                sacc[j][1] = __expf(sacc[j][1] - mn0);
                sacc[j][2] = __expf(sacc[j][2] - mn1);
                sacc[j][3] = __expf(sacc[j][3] - mn1);
                sum0 += sacc[j][0] + sacc[j][1];
                sum1 += sacc[j][2] + sacc[j][3];
            }
            sum0 += __shfl_xor_sync(0xffffffffu, sum0, 1);
            sum0 += __shfl_xor_sync(0xffffffffu, sum0, 2);
            sum1 += __shfl_xor_sync(0xffffffffu, sum1, 1);
            sum1 += __shfl_xor_sync(0xffffffffu, sum1, 2);
            l0 = l0 * al0 + sum0;
            l1 = l1 * al1 + sum1;
            #pragma unroll
            for (int jn = 0; jn < 8; jn++) {
                oacc[jn][0] *= al0; oacc[jn][1] *= al0;
                oacc[jn][2] *= al1; oacc[jn][3] *= al1;
            }

            uint32_t pa[4][4];
            #pragma unroll
            for (int jp = 0; jp < 4; jp++) {
                pa[jp][0] = packbf2(sacc[2 * jp][0],     sacc[2 * jp][1]);
                pa[jp][1] = packbf2(sacc[2 * jp][2],     sacc[2 * jp][3]);
                pa[jp][2] = packbf2(sacc[2 * jp + 1][0], sacc[2 * jp + 1][1]);
                pa[jp][3] = packbf2(sacc[2 * jp + 1][2], sacc[2 * jp + 1][3]);
            }
            #pragma unroll
            for (int jp = 0; jp < 4; jp++) {
                #pragma unroll
                for (int jn = 0; jn < 8; jn++) {
                    uint32_t b0, b1;
                    ldm_x2_t(b0, b1, smem_u32(vsh + (jp * 16 + (lane & 15)) * FA_LDS + jn * 8));
                    uint32_t bb[2] = {b0, b1};
                    mma16816(oacc[jn], pa[jp], bb);
                }
            }
        }
        __syncthreads();
    }

    float inv0 = 1.f / l0, inv1 = 1.f / l1;
    int rA = lane >> 2;
    int tok0 = b * SEQ + q0 + w * 16 + rA;
    int colb = h * HD + (lane & 3) * 2;
    #pragma unroll
    for (int jn = 0; jn < 8; jn++) {
        __nv_bfloat162 v0 = __floats2bfloat162_rn(oacc[jn][0] * inv0, oacc[jn][1] * inv0);
        __nv_bfloat162 v1 = __floats2bfloat162_rn(oacc[jn][2] * inv1, oacc[jn][3] * inv1);
        *(__nv_bfloat162*)(xo + (size_t)tok0 * DIMC + colb + jn * 8) = v0;
        *(__nv_bfloat162*)(xo + (size_t)(tok0 + 8) * DIMC + colb + jn * 8) = v1;
    }
}

/* ---------------- reductions ------------------------------------------------ */
__device__ __forceinline__ float blockReduceSum(float val) {
    __shared__ float sh[32];
    int lane = threadIdx.x & 31, wid = threadIdx.x >> 5;
    #pragma unroll
    for (int o = 16; o > 0; o >>= 1) val += __shfl_down_sync(0xffffffffu, val, o);
    if (lane == 0) sh[wid] = val;
    __syncthreads();
    val = (threadIdx.x < (blockDim.x >> 5)) ? sh[threadIdx.x] : 0.f;
    if (wid == 0) {
        #pragma unroll
        for (int o = 16; o > 0; o >>= 1) val += __shfl_down_sync(0xffffffffu, val, o);
        if (lane == 0) sh[0] = val;
    }
    __syncthreads();
    float r = sh[0];
    __syncthreads();
    return r;
}

/* ---------------- LayerNorm -> bf16 ---------------------------------------- */
__global__ void ln_rows(const float* __restrict__ x, const float* __restrict__ g,
                        const float* __restrict__ b, bf16* __restrict__ outb) {
    int row = blockIdx.x, t = threadIdx.x;
    const float* xr = x + (size_t)row * DIMC;
    float v[4]; float s = 0.f;
    #pragma unroll
    for (int i = 0; i < 4; i++) { v[i] = xr[i * 256 + t]; s += v[i]; }
    float mean = blockReduceSum(s) * (1.f / DIMC);
    float s2 = 0.f;
    #pragma unroll
    for (int i = 0; i < 4; i++) { float d = v[i] - mean; s2 += d * d; }
    float inv = rsqrtf(blockReduceSum(s2) * (1.f / DIMC) + 1e-5f);
    bf16* orow = outb + (size_t)row * DIMC;
    #pragma unroll
    for (int i = 0; i < 4; i++) {
        int c = i * 256 + t;
        orow[c] = __float2bfloat16((v[i] - mean) * inv * g[c] + b[c]);
    }
}

/* ---------------- all four weight conversions in one launch ----------------- */
__global__ void convert_all(const float* __restrict__ W1, const float* __restrict__ projW,
                            const float* __restrict__ mlpW, const float* __restrict__ W2,
                            bf16* __restrict__ d1, bf16* __restrict__ d2,
                            bf16* __restrict__ d3, bf16* __restrict__ d4) {
    int z = blockIdx.y;
    const float* src; bf16* dst; int srows, scols, dcols; long long total;
    if (z == 0)      { src = W1;    dst = d1; srows = DIMC;   scols = F1N;  dcols = F1NP; total = (long long)DIMC * F1NP; }
    else if (z == 1) { src = projW; dst = d2; srows = DIMC;   scols = DIMC; dcols = DIMC; total = (long long)DIMC * DIMC; }
    else if (z == 2) { src = mlpW;  dst = d3; srows = MLPH;   scols = DIMC; dcols = DIMC; total = (long long)MLPKP * DIMC; }
    else             { src = W2;    dst = d4; srows = 2*DIMC; scols = DIMC; dcols = DIMC; total = (long long)2 * DIMC * DIMC; }
    long long i = (long long)blockIdx.x * 256 + threadIdx.x;
    if (i >= total) return;
    int r = (int)(i / dcols), c = (int)(i % dcols);
    float v = (r < srows && c < scols) ? src[(size_t)r * scols + c] : 0.f;
    dst[i] = __float2bfloat16(v);
}

/* ---------------- launcher -------------------------------------------------- */
extern "C" void kernel_launch(void* const* d_in, const int* in_sizes, int n_in,
                              void* d_out, int out_size) {
    const float* x      = (const float*)d_in[0];
    const float* norm_g = (const float*)d_in[1];
    const float* norm_b = (const float*)d_in[2];
    const float* W1     = (const float*)d_in[3];
    const float* b1     = (const float*)d_in[4];
    const float* qn_g   = (const float*)d_in[5];
    const float* qn_b   = (const float*)d_in[6];
    const float* kn_g   = (const float*)d_in[7];
    const float* kn_b   = (const float*)d_in[8];
    const float* projW  = (const float*)d_in[9];
    const float* projb  = (const float*)d_in[10];
    const float* mlpW   = (const float*)d_in[11];
    const float* W2     = (const float*)d_in[12];
    const float* b2     = (const float*)d_in[13];
    const float* ls_g   = (const float*)d_in[14];
    float* out = (float*)d_out;

    unsigned char* base = 0;
    cudaGetSymbolAddress((void**)&base, g_scratch);

    bf16*  p_normx = (bf16*)(base + OF_NORMX);
    bf16*  p_W1b   = (bf16*)(base + OF_W1B);
    bf16*  p_projWb= (bf16*)(base + OF_PROJW);
    bf16*  p_mlpWb = (bf16*)(base + OF_MLPW);
    bf16*  p_W2b   = (bf16*)(base + OF_W2B);
    bf16*  p_f1q   = (bf16*)(base + OF_F1Q);
    bf16*  p_xo    = (bf16*)(base + OF_XO);
    bf16*  p_gelu  = (bf16*)(base + OF_GELU);
    bf16*  p_comb  = (bf16*)(base + OF_COMB);

    static int attr_done = 0;
    if (!attr_done) {
        cudaFuncSetAttribute(hgemm<1>,  cudaFuncAttributeMaxDynamicSharedMemorySize, HG_SMEM);
        cudaFuncSetAttribute(hgemm<2>,  cudaFuncAttributeMaxDynamicSharedMemorySize, HG_SMEM);
        cudaFuncSetAttribute(hgemm<3>,  cudaFuncAttributeMaxDynamicSharedMemorySize, HG_SMEM);
        cudaFuncSetAttribute(hgemm_pair, cudaFuncAttributeMaxDynamicSharedMemorySize, HG_SMEM);
        cudaFuncSetAttribute(fattn,     cudaFuncAttributeMaxDynamicSharedMemorySize, FA_SMEM);
        attr_done = 1;
    }

    /* 0. weight conversions */
    convert_all<<<dim3((unsigned)(((long long)DIMC * F1NP + 255) / 256), 4), 256>>>(
        W1, projW, mlpW, W2, p_W1b, p_projWb, p_mlpWb, p_W2b);

    /* 1. layernorm -> bf16 */
    ln_rows<<<TOK, 256>>>(x, norm_g, norm_b, p_normx);

    /* 2. f1 = normx @ W1 + b1 : qkv -> f1q bf16, gelu -> p_gelu bf16 */
    hgemm<3><<<dim3(F1NP / 128, TOK / 128), 256, HG_SMEM>>>(
        p_normx, p_W1b, p_f1q, p_gelu, DIMC, DIMC, F1NP, 0, b1, F1N, 0, 0);

    /* 3. flash attention with fused q/k LN -> xo (token-major) */
    fattn<<<dim3(SEQ / 128, BH), 256, FA_SMEM>>>(p_f1q, p_xo, qn_g, qn_b, kn_g, kn_b);

    /* 4. merged proj + mlp -> comb */
    hgemm_pair<<<dim3(DIMC / 128, TOK / 128, 2), 256, HG_SMEM>>>(
        p_xo, p_projWb, p_gelu, p_mlpWb, p_comb, projb);

    /* 5. out = x + (comb @ W2 + b2) * ls_g  fp32 */
    hgemm<2><<<dim3(DIMC / 128, TOK / 128), 256, HG_SMEM>>>(
        p_comb, p_W2b, out, 0, 2 * DIMC, 2 * DIMC, DIMC, DIMC, b2, DIMC, x, ls_g);
}

// round 11
// speedup vs baseline: 1.0512x; 1.0074x over previous
#include <cuda_runtime.h>
#include <cuda_bf16.h>
#include <math.h>
#include <stdint.h>

#define DIMC   1024
#define HEADS  16
#define HD     64
#define MLPH   716
#define F1N    3788
#define F1NP   3840
#define QKVN   3072
#define MLPKP  768
#define BATCH  4
#define SEQ    1024
#define TOK    (BATCH*SEQ)
#define BH     (BATCH*HEADS)

typedef __nv_bfloat16 bf16;

/* ---------------- single scratch arena ------------------------------------- */
#define SZ_NORMX ((size_t)TOK*DIMC*2)
#define SZ_W1B   ((size_t)DIMC*F1NP*2)
#define SZ_PROJW ((size_t)DIMC*DIMC*2)
#define SZ_MLPW  ((size_t)MLPKP*DIMC*2)
#define SZ_W2B   ((size_t)2*DIMC*DIMC*2)
#define SZ_F1Q   ((size_t)TOK*QKVN*2)
#define SZ_XO    ((size_t)TOK*DIMC*2)
#define SZ_GELU  ((size_t)TOK*MLPKP*2)
#define SZ_COMB  ((size_t)TOK*2*DIMC*2)

#define OF_NORMX ((size_t)0)
#define OF_W1B   (OF_NORMX + SZ_NORMX)
#define OF_PROJW (OF_W1B   + SZ_W1B)
#define OF_MLPW  (OF_PROJW + SZ_PROJW)
#define OF_W2B   (OF_MLPW  + SZ_MLPW)
#define OF_F1Q   (OF_W2B   + SZ_W2B)
#define OF_XO    (OF_F1Q   + SZ_F1Q)
#define OF_GELU  (OF_XO    + SZ_XO)
#define OF_COMB  (OF_GELU  + SZ_GELU)
#define OF_END   (OF_COMB  + SZ_COMB)

__device__ __align__(256) unsigned char g_scratch[OF_END];

/* ---------------- PTX helpers ---------------------------------------------- */
__device__ __forceinline__ uint32_t smem_u32(const void* p) {
    return (uint32_t)__cvta_generic_to_shared(p);
}
__device__ __forceinline__ void cp16(uint32_t dst, const void* src) {
    asm volatile("cp.async.cg.shared.global [%0], [%1], 16;\n" :: "r"(dst), "l"(src));
}
__device__ __forceinline__ void cp_commit() { asm volatile("cp.async.commit_group;\n"); }
__device__ __forceinline__ void cp_wait0()  { asm volatile("cp.async.wait_group 0;\n"); }
__device__ __forceinline__ void cp_wait1()  { asm volatile("cp.async.wait_group 1;\n"); }
__device__ __forceinline__ void cp_wait2()  { asm volatile("cp.async.wait_group 2;\n"); }
__device__ __forceinline__ void ldm_x4(uint32_t& r0, uint32_t& r1, uint32_t& r2, uint32_t& r3, uint32_t a) {
    asm volatile("ldmatrix.sync.aligned.m8n8.x4.shared.b16 {%0,%1,%2,%3}, [%4];\n"
                 : "=r"(r0), "=r"(r1), "=r"(r2), "=r"(r3) : "r"(a));
}
__device__ __forceinline__ void ldm_x4_t(uint32_t& r0, uint32_t& r1, uint32_t& r2, uint32_t& r3, uint32_t a) {
    asm volatile("ldmatrix.sync.aligned.m8n8.x4.trans.shared.b16 {%0,%1,%2,%3}, [%4];\n"
                 : "=r"(r0), "=r"(r1), "=r"(r2), "=r"(r3) : "r"(a));
}
__device__ __forceinline__ void ldm_x2(uint32_t& r0, uint32_t& r1, uint32_t a) {
    asm volatile("ldmatrix.sync.aligned.m8n8.x2.shared.b16 {%0,%1}, [%2];\n"
                 : "=r"(r0), "=r"(r1) : "r"(a));
}
__device__ __forceinline__ void ldm_x2_t(uint32_t& r0, uint32_t& r1, uint32_t a) {
    asm volatile("ldmatrix.sync.aligned.m8n8.x2.trans.shared.b16 {%0,%1}, [%2];\n"
                 : "=r"(r0), "=r"(r1) : "r"(a));
}
__device__ __forceinline__ void mma16816(float* c, const uint32_t* a, const uint32_t* b) {
    asm volatile("mma.sync.aligned.m16n8k16.row.col.f32.bf16.bf16.f32 "
                 "{%0,%1,%2,%3}, {%4,%5,%6,%7}, {%8,%9}, {%0,%1,%2,%3};\n"
                 : "+f"(c[0]), "+f"(c[1]), "+f"(c[2]), "+f"(c[3])
                 : "r"(a[0]), "r"(a[1]), "r"(a[2]), "r"(a[3]), "r"(b[0]), "r"(b[1]));
}
__device__ __forceinline__ uint32_t packbf2(float lo, float hi) {
    __nv_bfloat162 p = __floats2bfloat162_rn(lo, hi);
    return *(uint32_t*)&p;
}

/* ---------------- hgemm: 128x128x32 tiles, 3-stage cp.async ----------------
   A [M,K] row-major bf16, B [K,N] row-major bf16.
   EPI 1: bf16 C = acc + bias
   EPI 2: f32  C = resid + (acc+bias)*ls
   EPI 3: f1 dual: n<3072 -> bf16 Cv[m*3072+n]  n>=3072 -> C2v gelu          */
#define HG_ASZ  (128*40)
#define HG_BSS  136
#define HG_BSZ  (32*HG_BSS)
#define HG_SMEM ((3*(HG_ASZ + HG_BSZ))*2)

__device__ __forceinline__ void hg_prefetch(
        const bf16* __restrict__ A, const bf16* __restrict__ B,
        bf16* As, bf16* Bs, int k0, int bm, int bn, int lda, int ldb, int t) {
    int ar = t >> 1, ac = (t & 1) * 16;
    uint32_t ad = smem_u32(As + ar * 40 + ac);
    const bf16* asrc = A + (size_t)(bm + ar) * lda + k0 + ac;
    cp16(ad, asrc);
    cp16(ad + 16, asrc + 8);
    int br = t >> 3, bc = (t & 7) * 16;
    uint32_t bd = smem_u32(Bs + br * HG_BSS + bc);
    const bf16* bsrc = B + (size_t)(k0 + br) * ldb + bn + bc;
    cp16(bd, bsrc);
    cp16(bd + 16, bsrc + 8);
}

__device__ __forceinline__ void hg_mainloop(
        const bf16* __restrict__ A, const bf16* __restrict__ B,
        bf16* As, bf16* Bs, float acc[4][4][4],
        int K, int lda, int ldb, int bm, int bn, int t, int lane, int wm, int wn) {
    const int KT = K / 32;
    hg_prefetch(A, B, As, Bs, 0, bm, bn, lda, ldb, t);
    cp_commit();
    if (KT > 1) hg_prefetch(A, B, As + HG_ASZ, Bs + HG_BSZ, 32, bm, bn, lda, ldb, t);
    cp_commit();

    for (int kt = 0; kt < KT; kt++) {
        if (kt + 2 < KT) {
            int st = (kt + 2) % 3;
            hg_prefetch(A, B, As + st * HG_ASZ, Bs + st * HG_BSZ, (kt + 2) * 32, bm, bn, lda, ldb, t);
        }
        cp_commit();
        cp_wait2();
        __syncthreads();

        int s = kt % 3;
        bf16* as = As + s * HG_ASZ;
        bf16* bs = Bs + s * HG_BSZ;
        #pragma unroll
        for (int kk = 0; kk < 2; kk++) {
            uint32_t afr[4][4];
            #pragma unroll
            for (int i = 0; i < 4; i++) {
                uint32_t a = smem_u32(as + (wm + i * 16 + (lane & 15)) * 40 + kk * 16 + (lane >> 4) * 8);
                ldm_x4(afr[i][0], afr[i][1], afr[i][2], afr[i][3], a);
            }
            uint32_t bfr[4][2];
            #pragma unroll
            for (int j = 0; j < 4; j++) {
                uint32_t a = smem_u32(bs + (kk * 16 + (lane & 15)) * HG_BSS + wn + j * 8);
                ldm_x2_t(bfr[j][0], bfr[j][1], a);
            }
            #pragma unroll
            for (int i = 0; i < 4; i++)
                #pragma unroll
                for (int j = 0; j < 4; j++)
                    mma16816(acc[i][j], afr[i], bfr[j]);
        }
        __syncthreads();
    }
}

template<int EPI>
__global__ __launch_bounds__(256) void hgemm(
        const bf16* __restrict__ A, const bf16* __restrict__ B,
        void* __restrict__ Cv, void* __restrict__ C2v,
        int K, int lda, int ldb, int ldc,
        const float* __restrict__ bias, int nbias,
        const float* __restrict__ resid, const float* __restrict__ ls) {
    extern __shared__ __align__(16) bf16 sm[];
    bf16* As = sm;
    bf16* Bs = sm + 3 * HG_ASZ;

    const int t = threadIdx.x;
    const int lane = t & 31, warp = t >> 5;
    const int bm = blockIdx.y * 128;
    const int bn = blockIdx.x * 128;
    const int wm = (warp >> 2) * 64;
    const int wn = (warp & 3) * 32;

    float acc[4][4][4];
    #pragma unroll
    for (int i = 0; i < 4; i++)
        #pragma unroll
        for (int j = 0; j < 4; j++)
            #pragma unroll
            for (int e = 0; e < 4; e++) acc[i][j][e] = 0.f;

    hg_mainloop(A, B, As, Bs, acc, K, lda, ldb, bm, bn, t, lane, wm, wn);

    #pragma unroll
    for (int i = 0; i < 4; i++) {
        int m0 = bm + wm + i * 16 + (lane >> 2);
        #pragma unroll
        for (int j = 0; j < 4; j++) {
            int n0 = bn + wn + j * 8 + (lane & 3) * 2;
            float b0 = 0.f, b1v = 0.f;
            if (bias != 0) {
                if (n0 < nbias)     b0  = bias[n0];
                if (n0 + 1 < nbias) b1v = bias[n0 + 1];
            }
            #pragma unroll
            for (int eh = 0; eh < 2; eh++) {
                int m = m0 + eh * 8;
                float v0 = acc[i][j][eh * 2 + 0] + b0;
                float v1 = acc[i][j][eh * 2 + 1] + b1v;
                if (EPI == 1) {
                    *(__nv_bfloat162*)((bf16*)Cv + (size_t)m * ldc + n0) =
                        __floats2bfloat162_rn(v0, v1);
                } else if (EPI == 2) {
                    const float2 r = *(const float2*)(resid + (size_t)m * ldc + n0);
                    float2 o;
                    o.x = r.x + v0 * ls[n0];
                    o.y = r.y + v1 * ls[n0 + 1];
                    *(float2*)((float*)Cv + (size_t)m * ldc + n0) = o;
                } else {  /* EPI 3 */
                    if (bn >= QKVN) {
                        float g0 = 0.5f * v0 * (1.f + erff(v0 * 0.70710678118654752f));
                        float g1 = 0.5f * v1 * (1.f + erff(v1 * 0.70710678118654752f));
                        *(__nv_bfloat162*)((bf16*)C2v + (size_t)m * MLPKP + (n0 - QKVN)) =
                            __floats2bfloat162_rn(g0, g1);
                    } else {
                        *(__nv_bfloat162*)((bf16*)Cv + (size_t)m * QKVN + n0) =
                            __floats2bfloat162_rn(v0, v1);
                    }
                }
            }
        }
    }
}

/* merged proj (z=0) + mlp (z=1) GEMM -> comb (ldc = 2048), bf16 out */
__global__ __launch_bounds__(256) void hgemm_pair(
        const bf16* __restrict__ A0, const bf16* __restrict__ B0,
        const bf16* __restrict__ A1, const bf16* __restrict__ B1,
        bf16* __restrict__ C, const float* __restrict__ bias0) {
    extern __shared__ __align__(16) bf16 sm[];
    bf16* As = sm;
    bf16* Bs = sm + 3 * HG_ASZ;

    const int t = threadIdx.x;
    const int lane = t & 31, warp = t >> 5;
    const int z = blockIdx.z;
    const bf16* A = z ? A1 : A0;
    const bf16* B = z ? B1 : B0;
    const int K = z ? MLPKP : DIMC;
    const float* bias = z ? (const float*)0 : bias0;
    const int bm = blockIdx.y * 128;
    const int bn = blockIdx.x * 128;
    const int wm = (warp >> 2) * 64;
    const int wn = (warp & 3) * 32;

    float acc[4][4][4];
    #pragma unroll
    for (int i = 0; i < 4; i++)
        #pragma unroll
        for (int j = 0; j < 4; j++)
            #pragma unroll
            for (int e = 0; e < 4; e++) acc[i][j][e] = 0.f;

    hg_mainloop(A, B, As, Bs, acc, K, K, DIMC, bm, bn, t, lane, wm, wn);

    const int nout = z * DIMC;
    #pragma unroll
    for (int i = 0; i < 4; i++) {
        int m0 = bm + wm + i * 16 + (lane >> 2);
        #pragma unroll
        for (int j = 0; j < 4; j++) {
            int n0 = bn + wn + j * 8 + (lane & 3) * 2;
            float b0 = bias ? bias[n0] : 0.f;
            float b1v = bias ? bias[n0 + 1] : 0.f;
            #pragma unroll
            for (int eh = 0; eh < 2; eh++) {
                int m = m0 + eh * 8;
                *(__nv_bfloat162*)(C + (size_t)m * (2 * DIMC) + nout + n0) =
                    __floats2bfloat162_rn(acc[i][j][eh * 2 + 0] + b0,
                                          acc[i][j][eh * 2 + 1] + b1v);
            }
        }
    }
}

/* ---------------- flash attention, fused q/k LN, 64-key chunks, x4 loads ---- */
#define FA_LDS  72
#define FA_TSZ  (128*FA_LDS)
#define FA_SMEM ((5*FA_TSZ)*2)

__device__ __forceinline__ void fa_load_tile(const bf16* __restrict__ src, bf16* dst,
                                             int t, int ld) {
    #pragma unroll
    for (int i = 0; i < 4; i++) {
        int idx = t + i * 256;
        int r = idx >> 3, c = (idx & 7) * 8;
        cp16(smem_u32(dst + r * FA_LDS + c), src + (size_t)r * ld + c);
    }
}

/* two-pass per-row LN over a 128x64 smem tile (2 threads per row) */
__device__ __forceinline__ void fa_ln_tile(bf16* tile, const float* g_s,
                                           const float* b_s, int t) {
    int r = t >> 1, h2 = t & 1;
    bf16* p = tile + r * FA_LDS + h2 * 32;
    float s = 0.f, s2 = 0.f;
    #pragma unroll
    for (int i = 0; i < 4; i++) {
        uint4 u = *(uint4*)(p + i * 8);
        const __nv_bfloat162* pr = (const __nv_bfloat162*)&u;
        #pragma unroll
        for (int j = 0; j < 4; j++) {
            float2 f2 = __bfloat1622float2(pr[j]);
            s += f2.x + f2.y;
            s2 += f2.x * f2.x + f2.y * f2.y;
        }
    }
    s  += __shfl_xor_sync(0xffffffffu, s, 1);
    s2 += __shfl_xor_sync(0xffffffffu, s2, 1);
    float m = s * (1.f / HD);
    float var = s2 * (1.f / HD) - m * m;
    float inv = rsqrtf(var + 1e-5f);
    int cb = h2 * 32;
    #pragma unroll
    for (int i = 0; i < 4; i++) {
        uint4 u = *(uint4*)(p + i * 8);
        __nv_bfloat162* pr = (__nv_bfloat162*)&u;
        #pragma unroll
        for (int j = 0; j < 4; j++) {
            float2 f2 = __bfloat1622float2(pr[j]);
            int c = cb + i * 8 + j * 2;
            pr[j] = __floats2bfloat162_rn((f2.x - m) * inv * g_s[c] + b_s[c],
                                          (f2.y - m) * inv * g_s[c + 1] + b_s[c + 1]);
        }
        *(uint4*)(p + i * 8) = u;
    }
}

__global__ __launch_bounds__(256, 2) void fattn(
        const bf16* __restrict__ f1q, bf16* __restrict__ xo,
        const float* __restrict__ qg, const float* __restrict__ qb,
        const float* __restrict__ kg, const float* __restrict__ kb) {
    extern __shared__ __align__(16) bf16 fsm[];
    bf16* Qs = fsm;
    bf16* Ks = fsm + FA_TSZ;
    bf16* Vs = fsm + 3 * FA_TSZ;
    __shared__ float qg_s[64], qb_s[64], kg_s[64], kb_s[64];

    const int t = threadIdx.x;
    const int lane = t & 31, w = t >> 5;
    const int bh = blockIdx.y;
    const int q0 = blockIdx.x * 128;
    const int b = bh / HEADS, h = bh % HEADS;
    const bf16* rowbase = f1q + (size_t)(b * SEQ) * QKVN;
    const bf16* qp = rowbase + (size_t)q0 * QKVN + h * HD;
    const bf16* kp = rowbase + DIMC + h * HD;
    const bf16* vp = rowbase + 2 * DIMC + h * HD;

    /* fold 1/sqrt(d)=0.125 into q's LN gamma/beta */
    if (t < 64) {
        qg_s[t] = qg[t] * 0.125f; qb_s[t] = qb[t] * 0.125f;
        kg_s[t] = kg[t];          kb_s[t] = kb[t];
    }

    fa_load_tile(qp, Qs, t, QKVN);
    cp_commit();
    fa_load_tile(kp, Ks, t, QKVN);
    fa_load_tile(vp, Vs, t, QKVN);
    cp_commit();

    cp_wait1();
    __syncthreads();
    fa_ln_tile(Qs, qg_s, qb_s, t);
    __syncthreads();
    uint32_t qf[4][4];
    #pragma unroll
    for (int kk = 0; kk < 4; kk++) {
        uint32_t a = smem_u32(Qs + (w * 16 + (lane & 15)) * FA_LDS + kk * 16 + (lane >> 4) * 8);
        ldm_x4(qf[kk][0], qf[kk][1], qf[kk][2], qf[kk][3], a);
    }

    float oacc[8][4];
    #pragma unroll
    for (int jn = 0; jn < 8; jn++)
        #pragma unroll
        for (int e = 0; e < 4; e++) oacc[jn][e] = 0.f;
    float m0r = -1e30f, m1r = -1e30f, l0 = 0.f, l1 = 0.f;

    for (int c = 0; c < SEQ / 128; c++) {
        if (c + 1 < SEQ / 128) {
            int sn = (c + 1) & 1;
            fa_load_tile(kp + (size_t)(c + 1) * 128 * QKVN, Ks + sn * FA_TSZ, t, QKVN);
            fa_load_tile(vp + (size_t)(c + 1) * 128 * QKVN, Vs + sn * FA_TSZ, t, QKVN);
        }
        cp_commit();
        cp_wait1();
        __syncthreads();

        const int s = c & 1;
        bf16* ks = Ks + s * FA_TSZ;
        bf16* vs = Vs + s * FA_TSZ;

        fa_ln_tile(ks, kg_s, kb_s, t);
        __syncthreads();

        /* two 64-key halves: smaller live register set */
        #pragma unroll
        for (int half = 0; half < 2; half++) {
            bf16* ksh = ks + half * 64 * FA_LDS;
            bf16* vsh = vs + half * 64 * FA_LDS;

            float sacc[8][4];
            #pragma unroll
            for (int j = 0; j < 8; j++)
                #pragma unroll
                for (int e = 0; e < 4; e++) sacc[j][e] = 0.f;
            /* S = (q*scale) @ K^T : x4 batched loads (lanes16-31 fetch next j) */
            #pragma unroll
            for (int kk = 0; kk < 4; kk++) {
                #pragma unroll
                for (int j2 = 0; j2 < 4; j2++) {
                    uint32_t r0, r1, r2, r3;
                    uint32_t a = smem_u32(ksh + (j2 * 16 + (lane >> 4) * 8 + (lane & 7)) * FA_LDS
                                          + kk * 16 + ((lane >> 3) & 1) * 8);
                    ldm_x4(r0, r1, r2, r3, a);
                    uint32_t bb0[2] = {r0, r1};
                    uint32_t bb1[2] = {r2, r3};
                    mma16816(sacc[2 * j2],     qf[kk], bb0);
                    mma16816(sacc[2 * j2 + 1], qf[kk], bb1);
                }
            }

            float mx0 = -1e30f, mx1 = -1e30f;
            #pragma unroll
            for (int j = 0; j < 8; j++) {
                mx0 = fmaxf(mx0, fmaxf(sacc[j][0], sacc[j][1]));
                mx1 = fmaxf(mx1, fmaxf(sacc[j][2], sacc[j][3]));
            }
            mx0 = fmaxf(mx0, __shfl_xor_sync(0xffffffffu, mx0, 1));
            mx0 = fmaxf(mx0, __shfl_xor_sync(0xffffffffu, mx0, 2));
            mx1 = fmaxf(mx1, __shfl_xor_sync(0xffffffffu, mx1, 1));
            mx1 = fmaxf(mx1, __shfl_xor_sync(0xffffffffu, mx1, 2));
            float mn0 = fmaxf(m0r, mx0), mn1 = fmaxf(m1r, mx1);
            float al0 = __expf(m0r - mn0), al1 = __expf(m1r - mn1);
            m0r = mn0; m1r = mn1;

            float sum0 = 0.f, sum1 = 0.f;
            #pragma unroll
            for (int j = 0; j < 8; j++) {
                sacc[j][0] = __expf(sacc[j][0] - mn0);
                sacc[j][1] = __expf(sacc[j][1] - mn0);
                sacc[j][2] = __expf(sacc[j][2] - mn1);
                sacc[j][3] = __expf(sacc[j][3] - mn1);
                sum0 += sacc[j][0] + sacc[j][1];
                sum1 += sacc[j][2] + sacc[j][3];
            }
            sum0 += __shfl_xor_sync(0xffffffffu, sum0, 1);
            sum0 += __shfl_xor_sync(0xffffffffu, sum0, 2);
            sum1 += __shfl_xor_sync(0xffffffffu, sum1, 1);
            sum1 += __shfl_xor_sync(0xffffffffu, sum1, 2);
            l0 = l0 * al0 + sum0;
            l1 = l1 * al1 + sum1;
            #pragma unroll
            for (int jn = 0; jn < 8; jn++) {
                oacc[jn][0] *= al0; oacc[jn][1] *= al0;
                oacc[jn][2] *= al1; oacc[jn][3] *= al1;
            }

            uint32_t pa[4][4];
            #pragma unroll
            for (int jp = 0; jp < 4; jp++) {
                pa[jp][0] = packbf2(sacc[2 * jp][0],     sacc[2 * jp][1]);
                pa[jp][1] = packbf2(sacc[2 * jp][2],     sacc[2 * jp][3]);
                pa[jp][2] = packbf2(sacc[2 * jp + 1][0], sacc[2 * jp + 1][1]);
                pa[jp][3] = packbf2(sacc[2 * jp + 1][2], sacc[2 * jp + 1][3]);
            }
            /* P @ V : x4 trans batched loads (lanes16-31 fetch next jn) */
            #pragma unroll
            for (int jp = 0; jp < 4; jp++) {
                #pragma unroll
                for (int j2 = 0; j2 < 4; j2++) {
                    uint32_t r0, r1, r2, r3;
                    uint32_t a = smem_u32(vsh + (jp * 16 + (lane & 15)) * FA_LDS
                                          + (j2 * 2 + (lane >> 4)) * 8);
                    ldm_x4_t(r0, r1, r2, r3, a);
                    uint32_t bb0[2] = {r0, r1};
                    uint32_t bb1[2] = {r2, r3};
                    mma16816(oacc[2 * j2],     pa[jp], bb0);
                    mma16816(oacc[2 * j2 + 1], pa[jp], bb1);
                }
            }
        }
        __syncthreads();
    }

    float inv0 = 1.f / l0, inv1 = 1.f / l1;
    int rA = lane >> 2;
    int tok0 = b * SEQ + q0 + w * 16 + rA;
    int colb = h * HD + (lane & 3) * 2;
    #pragma unroll
    for (int jn = 0; jn < 8; jn++) {
        __nv_bfloat162 v0 = __floats2bfloat162_rn(oacc[jn][0] * inv0, oacc[jn][1] * inv0);
        __nv_bfloat162 v1 = __floats2bfloat162_rn(oacc[jn][2] * inv1, oacc[jn][3] * inv1);
        *(__nv_bfloat162*)(xo + (size_t)tok0 * DIMC + colb + jn * 8) = v0;
        *(__nv_bfloat162*)(xo + (size_t)(tok0 + 8) * DIMC + colb + jn * 8) = v1;
    }
}

/* ---------------- reductions ------------------------------------------------ */
__device__ __forceinline__ float blockReduceSum(float val) {
    __shared__ float sh[32];
    int lane = threadIdx.x & 31, wid = threadIdx.x >> 5;
    #pragma unroll
    for (int o = 16; o > 0; o >>= 1) val += __shfl_down_sync(0xffffffffu, val, o);
    if (lane == 0) sh[wid] = val;
    __syncthreads();
    val = (threadIdx.x < (blockDim.x >> 5)) ? sh[threadIdx.x] : 0.f;
    if (wid == 0) {
        #pragma unroll
        for (int o = 16; o > 0; o >>= 1) val += __shfl_down_sync(0xffffffffu, val, o);
        if (lane == 0) sh[0] = val;
    }
    __syncthreads();
    float r = sh[0];
    __syncthreads();
    return r;
}

/* ---------------- LayerNorm -> bf16 ---------------------------------------- */
__global__ void ln_rows(const float* __restrict__ x, const float* __restrict__ g,
                        const float* __restrict__ b, bf16* __restrict__ outb) {
    int row = blockIdx.x, t = threadIdx.x;
    const float* xr = x + (size_t)row * DIMC;
    float v[4]; float s = 0.f;
    #pragma unroll
    for (int i = 0; i < 4; i++) { v[i] = xr[i * 256 + t]; s += v[i]; }
    float mean = blockReduceSum(s) * (1.f / DIMC);
    float s2 = 0.f;
    #pragma unroll
    for (int i = 0; i < 4; i++) { float d = v[i] - mean; s2 += d * d; }
    float inv = rsqrtf(blockReduceSum(s2) * (1.f / DIMC) + 1e-5f);
    bf16* orow = outb + (size_t)row * DIMC;
    #pragma unroll
    for (int i = 0; i < 4; i++) {
        int c = i * 256 + t;
        orow[c] = __float2bfloat16((v[i] - mean) * inv * g[c] + b[c]);
    }
}

/* ---------------- all four weight conversions in one launch ----------------- */
__global__ void convert_all(const float* __restrict__ W1, const float* __restrict__ projW,
                            const float* __restrict__ mlpW, const float* __restrict__ W2,
                            bf16* __restrict__ d1, bf16* __restrict__ d2,
                            bf16* __restrict__ d3, bf16* __restrict__ d4) {
    int z = blockIdx.y;
    const float* src; bf16* dst; int srows, scols, dcols; long long total;
    if (z == 0)      { src = W1;    dst = d1; srows = DIMC;   scols = F1N;  dcols = F1NP; total = (long long)DIMC * F1NP; }
    else if (z == 1) { src = projW; dst = d2; srows = DIMC;   scols = DIMC; dcols = DIMC; total = (long long)DIMC * DIMC; }
    else if (z == 2) { src = mlpW;  dst = d3; srows = MLPH;   scols = DIMC; dcols = DIMC; total = (long long)MLPKP * DIMC; }
    else             { src = W2;    dst = d4; srows = 2*DIMC; scols = DIMC; dcols = DIMC; total = (long long)2 * DIMC * DIMC; }
    long long i = (long long)blockIdx.x * 256 + threadIdx.x;
    if (i >= total) return;
    int r = (int)(i / dcols), c = (int)(i % dcols);
    float v = (r < srows && c < scols) ? src[(size_t)r * scols + c] : 0.f;
    dst[i] = __float2bfloat16(v);
}

/* ---------------- launcher -------------------------------------------------- */
extern "C" void kernel_launch(void* const* d_in, const int* in_sizes, int n_in,
                              void* d_out, int out_size) {
    const float* x      = (const float*)d_in[0];
    const float* norm_g = (const float*)d_in[1];
    const float* norm_b = (const float*)d_in[2];
    const float* W1     = (const float*)d_in[3];
    const float* b1     = (const float*)d_in[4];
    const float* qn_g   = (const float*)d_in[5];
    const float* qn_b   = (const float*)d_in[6];
    const float* kn_g   = (const float*)d_in[7];
    const float* kn_b   = (const float*)d_in[8];
    const float* projW  = (const float*)d_in[9];
    const float* projb  = (const float*)d_in[10];
    const float* mlpW   = (const float*)d_in[11];
    const float* W2     = (const float*)d_in[12];
    const float* b2     = (const float*)d_in[13];
    const float* ls_g   = (const float*)d_in[14];
    float* out = (float*)d_out;

    unsigned char* base = 0;
    cudaGetSymbolAddress((void**)&base, g_scratch);

    bf16*  p_normx = (bf16*)(base + OF_NORMX);
    bf16*  p_W1b   = (bf16*)(base + OF_W1B);
    bf16*  p_projWb= (bf16*)(base + OF_PROJW);
    bf16*  p_mlpWb = (bf16*)(base + OF_MLPW);
    bf16*  p_W2b   = (bf16*)(base + OF_W2B);
    bf16*  p_f1q   = (bf16*)(base + OF_F1Q);
    bf16*  p_xo    = (bf16*)(base + OF_XO);
    bf16*  p_gelu  = (bf16*)(base + OF_GELU);
    bf16*  p_comb  = (bf16*)(base + OF_COMB);

    static int attr_done = 0;
    if (!attr_done) {
        cudaFuncSetAttribute(hgemm<1>,  cudaFuncAttributeMaxDynamicSharedMemorySize, HG_SMEM);
        cudaFuncSetAttribute(hgemm<2>,  cudaFuncAttributeMaxDynamicSharedMemorySize, HG_SMEM);
        cudaFuncSetAttribute(hgemm<3>,  cudaFuncAttributeMaxDynamicSharedMemorySize, HG_SMEM);
        cudaFuncSetAttribute(hgemm_pair, cudaFuncAttributeMaxDynamicSharedMemorySize, HG_SMEM);
        cudaFuncSetAttribute(fattn,     cudaFuncAttributeMaxDynamicSharedMemorySize, FA_SMEM);
        attr_done = 1;
    }

    /* 0. weight conversions */
    convert_all<<<dim3((unsigned)(((long long)DIMC * F1NP + 255) / 256), 4), 256>>>(
        W1, projW, mlpW, W2, p_W1b, p_projWb, p_mlpWb, p_W2b);

    /* 1. layernorm -> bf16 */
    ln_rows<<<TOK, 256>>>(x, norm_g, norm_b, p_normx);

    /* 2. f1 = normx @ W1 + b1 : qkv -> f1q bf16, gelu -> p_gelu bf16 */
    hgemm<3><<<dim3(F1NP / 128, TOK / 128), 256, HG_SMEM>>>(
        p_normx, p_W1b, p_f1q, p_gelu, DIMC, DIMC, F1NP, 0, b1, F1N, 0, 0);

    /* 3. flash attention with fused q/k LN -> xo (token-major) */
    fattn<<<dim3(SEQ / 128, BH), 256, FA_SMEM>>>(p_f1q, p_xo, qn_g, qn_b, kn_g, kn_b);

    /* 4. merged proj + mlp -> comb */
    hgemm_pair<<<dim3(DIMC / 128, TOK / 128, 2), 256, HG_SMEM>>>(
        p_xo, p_projWb, p_gelu, p_mlpWb, p_comb, projb);

    /* 5. out = x + (comb @ W2 + b2) * ls_g  fp32 */
    hgemm<2><<<dim3(DIMC / 128, TOK / 128), 256, HG_SMEM>>>(
        p_comb, p_W2b, out, 0, 2 * DIMC, 2 * DIMC, DIMC, DIMC, b2, DIMC, x, ls_g);
}

// round 12
// speedup vs baseline: 1.1216x; 1.0670x over previous
#include <cuda_runtime.h>
#include <cuda_bf16.h>
#include <math.h>
#include <stdint.h>

#define DIMC   1024
#define HEADS  16
#define HD     64
#define MLPH   716
#define F1N    3788
#define F1NP   3840
#define QKVN   3072
#define MLPKP  768
#define BATCH  4
#define SEQ    1024
#define TOK    (BATCH*SEQ)
#define BH     (BATCH*HEADS)

typedef __nv_bfloat16 bf16;

/* ---------------- single scratch arena ------------------------------------- */
#define SZ_NORMX ((size_t)TOK*DIMC*2)
#define SZ_W1B   ((size_t)DIMC*F1NP*2)
#define SZ_PROJW ((size_t)DIMC*DIMC*2)
#define SZ_MLPW  ((size_t)MLPKP*DIMC*2)
#define SZ_W2B   ((size_t)2*DIMC*DIMC*2)
#define SZ_F1Q   ((size_t)TOK*QKVN*2)
#define SZ_XO    ((size_t)TOK*DIMC*2)
#define SZ_GELU  ((size_t)TOK*MLPKP*2)
#define SZ_COMB  ((size_t)TOK*2*DIMC*2)

#define OF_NORMX ((size_t)0)
#define OF_W1B   (OF_NORMX + SZ_NORMX)
#define OF_PROJW (OF_W1B   + SZ_W1B)
#define OF_MLPW  (OF_PROJW + SZ_PROJW)
#define OF_W2B   (OF_MLPW  + SZ_MLPW)
#define OF_F1Q   (OF_W2B   + SZ_W2B)
#define OF_XO    (OF_F1Q   + SZ_F1Q)
#define OF_GELU  (OF_XO    + SZ_XO)
#define OF_COMB  (OF_GELU  + SZ_GELU)
#define OF_END   (OF_COMB  + SZ_COMB)

__device__ __align__(256) unsigned char g_scratch[OF_END];

/* ---------------- PTX helpers ---------------------------------------------- */
__device__ __forceinline__ uint32_t smem_u32(const void* p) {
    return (uint32_t)__cvta_generic_to_shared(p);
}
__device__ __forceinline__ void cp16(uint32_t dst, const void* src) {
    asm volatile("cp.async.cg.shared.global [%0], [%1], 16;\n" :: "r"(dst), "l"(src));
}
__device__ __forceinline__ void cp_commit() { asm volatile("cp.async.commit_group;\n"); }
__device__ __forceinline__ void cp_wait0()  { asm volatile("cp.async.wait_group 0;\n"); }
__device__ __forceinline__ void cp_wait1()  { asm volatile("cp.async.wait_group 1;\n"); }
__device__ __forceinline__ void ldm_x4(uint32_t& r0, uint32_t& r1, uint32_t& r2, uint32_t& r3, uint32_t a) {
    asm volatile("ldmatrix.sync.aligned.m8n8.x4.shared.b16 {%0,%1,%2,%3}, [%4];\n"
                 : "=r"(r0), "=r"(r1), "=r"(r2), "=r"(r3) : "r"(a));
}
__device__ __forceinline__ void ldm_x4_t(uint32_t& r0, uint32_t& r1, uint32_t& r2, uint32_t& r3, uint32_t a) {
    asm volatile("ldmatrix.sync.aligned.m8n8.x4.trans.shared.b16 {%0,%1,%2,%3}, [%4];\n"
                 : "=r"(r0), "=r"(r1), "=r"(r2), "=r"(r3) : "r"(a));
}
__device__ __forceinline__ void ldm_x2_t(uint32_t& r0, uint32_t& r1, uint32_t a) {
    asm volatile("ldmatrix.sync.aligned.m8n8.x2.trans.shared.b16 {%0,%1}, [%2];\n"
                 : "=r"(r0), "=r"(r1) : "r"(a));
}
__device__ __forceinline__ void mma16816(float* c, const uint32_t* a, const uint32_t* b) {
    asm volatile("mma.sync.aligned.m16n8k16.row.col.f32.bf16.bf16.f32 "
                 "{%0,%1,%2,%3}, {%4,%5,%6,%7}, {%8,%9}, {%0,%1,%2,%3};\n"
                 : "+f"(c[0]), "+f"(c[1]), "+f"(c[2]), "+f"(c[3])
                 : "r"(a[0]), "r"(a[1]), "r"(a[2]), "r"(a[3]), "r"(b[0]), "r"(b[1]));
}
__device__ __forceinline__ uint32_t packbf2(float lo, float hi) {
    __nv_bfloat162 p = __floats2bfloat162_rn(lo, hi);
    return *(uint32_t*)&p;
}

/* ---------------- hgemm: 128x128x32 tiles, 3-stage, single-sync loop -------- */
#define HG_ASZ  (128*40)
#define HG_BSS  136
#define HG_BSZ  (32*HG_BSS)
#define HG_SMEM ((3*(HG_ASZ + HG_BSZ))*2)

__device__ __forceinline__ void hg_prefetch(
        const bf16* __restrict__ A, const bf16* __restrict__ B,
        bf16* As, bf16* Bs, int k0, int bm, int bn, int lda, int ldb, int t) {
    int ar = t >> 1, ac = (t & 1) * 16;
    uint32_t ad = smem_u32(As + ar * 40 + ac);
    const bf16* asrc = A + (size_t)(bm + ar) * lda + k0 + ac;
    cp16(ad, asrc);
    cp16(ad + 16, asrc + 8);
    int br = t >> 3, bc = (t & 7) * 16;
    uint32_t bd = smem_u32(Bs + br * HG_BSS + bc);
    const bf16* bsrc = B + (size_t)(k0 + br) * ldb + bn + bc;
    cp16(bd, bsrc);
    cp16(bd + 16, bsrc + 8);
}

/* single __syncthreads per K-iter: the stage-ready barrier also guards the
   overwrite of the stage that was read last iteration (prefetch issued after) */
__device__ __forceinline__ void hg_mainloop(
        const bf16* __restrict__ A, const bf16* __restrict__ B,
        bf16* As, bf16* Bs, float acc[4][4][4],
        int K, int lda, int ldb, int bm, int bn, int t, int lane, int wm, int wn) {
    const int KT = K / 32;
    hg_prefetch(A, B, As, Bs, 0, bm, bn, lda, ldb, t);
    cp_commit();
    if (KT > 1) hg_prefetch(A, B, As + HG_ASZ, Bs + HG_BSZ, 32, bm, bn, lda, ldb, t);
    cp_commit();

    for (int kt = 0; kt < KT; kt++) {
        cp_wait1();                 /* stage kt's group done (kt+1 may be pending) */
        __syncthreads();            /* publishes stage kt; also: everyone done reading stage (kt+2)%3 */
        if (kt + 2 < KT) {
            int st = (kt + 2) % 3;
            hg_prefetch(A, B, As + st * HG_ASZ, Bs + st * HG_BSZ, (kt + 2) * 32, bm, bn, lda, ldb, t);
        }
        cp_commit();

        int s = kt % 3;
        bf16* as = As + s * HG_ASZ;
        bf16* bs = Bs + s * HG_BSZ;
        #pragma unroll
        for (int kk = 0; kk < 2; kk++) {
            uint32_t afr[4][4];
            #pragma unroll
            for (int i = 0; i < 4; i++) {
                uint32_t a = smem_u32(as + (wm + i * 16 + (lane & 15)) * 40 + kk * 16 + (lane >> 4) * 8);
                ldm_x4(afr[i][0], afr[i][1], afr[i][2], afr[i][3], a);
            }
            uint32_t bfr[4][2];
            #pragma unroll
            for (int j = 0; j < 4; j++) {
                uint32_t a = smem_u32(bs + (kk * 16 + (lane & 15)) * HG_BSS + wn + j * 8);
                ldm_x2_t(bfr[j][0], bfr[j][1], a);
            }
            #pragma unroll
            for (int i = 0; i < 4; i++)
                #pragma unroll
                for (int j = 0; j < 4; j++)
                    mma16816(acc[i][j], afr[i], bfr[j]);
        }
    }
}

template<int EPI>
__global__ __launch_bounds__(256) void hgemm(
        const bf16* __restrict__ A, const bf16* __restrict__ B,
        void* __restrict__ Cv, void* __restrict__ C2v,
        int K, int lda, int ldb, int ldc,
        const float* __restrict__ bias, int nbias,
        const float* __restrict__ resid, const float* __restrict__ ls) {
    extern __shared__ __align__(16) bf16 sm[];
    bf16* As = sm;
    bf16* Bs = sm + 3 * HG_ASZ;

    const int t = threadIdx.x;
    const int lane = t & 31, warp = t >> 5;
    const int bm = blockIdx.y * 128;
    const int bn = blockIdx.x * 128;
    const int wm = (warp >> 2) * 64;
    const int wn = (warp & 3) * 32;

    float acc[4][4][4];
    #pragma unroll
    for (int i = 0; i < 4; i++)
        #pragma unroll
        for (int j = 0; j < 4; j++)
            #pragma unroll
            for (int e = 0; e < 4; e++) acc[i][j][e] = 0.f;

    hg_mainloop(A, B, As, Bs, acc, K, lda, ldb, bm, bn, t, lane, wm, wn);

    #pragma unroll
    for (int i = 0; i < 4; i++) {
        int m0 = bm + wm + i * 16 + (lane >> 2);
        #pragma unroll
        for (int j = 0; j < 4; j++) {
            int n0 = bn + wn + j * 8 + (lane & 3) * 2;
            float b0 = 0.f, b1v = 0.f;
            if (bias != 0) {
                if (n0 < nbias)     b0  = bias[n0];
                if (n0 + 1 < nbias) b1v = bias[n0 + 1];
            }
            #pragma unroll
            for (int eh = 0; eh < 2; eh++) {
                int m = m0 + eh * 8;
                float v0 = acc[i][j][eh * 2 + 0] + b0;
                float v1 = acc[i][j][eh * 2 + 1] + b1v;
                if (EPI == 1) {
                    *(__nv_bfloat162*)((bf16*)Cv + (size_t)m * ldc + n0) =
                        __floats2bfloat162_rn(v0, v1);
                } else if (EPI == 2) {
                    const float2 r = *(const float2*)(resid + (size_t)m * ldc + n0);
                    float2 o;
                    o.x = r.x + v0 * ls[n0];
                    o.y = r.y + v1 * ls[n0 + 1];
                    *(float2*)((float*)Cv + (size_t)m * ldc + n0) = o;
                } else {  /* EPI 3 */
                    if (bn >= QKVN) {
                        float g0 = 0.5f * v0 * (1.f + erff(v0 * 0.70710678118654752f));
                        float g1 = 0.5f * v1 * (1.f + erff(v1 * 0.70710678118654752f));
                        *(__nv_bfloat162*)((bf16*)C2v + (size_t)m * MLPKP + (n0 - QKVN)) =
                            __floats2bfloat162_rn(g0, g1);
                    } else {
                        *(__nv_bfloat162*)((bf16*)Cv + (size_t)m * QKVN + n0) =
                            __floats2bfloat162_rn(v0, v1);
                    }
                }
            }
        }
    }
}

/* ---------------- flash attention, fused q/k LN, 64-key chunks, x4 loads ---- */
#define FA_LDS  72
#define FA_TSZ  (128*FA_LDS)
#define FA_SMEM ((5*FA_TSZ)*2)

__device__ __forceinline__ void fa_load_tile(const bf16* __restrict__ src, bf16* dst,
                                             int t, int ld) {
    #pragma unroll
    for (int i = 0; i < 4; i++) {
        int idx = t + i * 256;
        int r = idx >> 3, c = (idx & 7) * 8;
        cp16(smem_u32(dst + r * FA_LDS + c), src + (size_t)r * ld + c);
    }
}

/* two-pass per-row LN over a 128x64 smem tile (2 threads per row) */
__device__ __forceinline__ void fa_ln_tile(bf16* tile, const float* g_s,
                                           const float* b_s, int t) {
    int r = t >> 1, h2 = t & 1;
    bf16* p = tile + r * FA_LDS + h2 * 32;
    float s = 0.f, s2 = 0.f;
    #pragma unroll
    for (int i = 0; i < 4; i++) {
        uint4 u = *(uint4*)(p + i * 8);
        const __nv_bfloat162* pr = (const __nv_bfloat162*)&u;
        #pragma unroll
        for (int j = 0; j < 4; j++) {
            float2 f2 = __bfloat1622float2(pr[j]);
            s += f2.x + f2.y;
            s2 += f2.x * f2.x + f2.y * f2.y;
        }
    }
    s  += __shfl_xor_sync(0xffffffffu, s, 1);
    s2 += __shfl_xor_sync(0xffffffffu, s2, 1);
    float m = s * (1.f / HD);
    float var = s2 * (1.f / HD) - m * m;
    float inv = rsqrtf(var + 1e-5f);
    int cb = h2 * 32;
    #pragma unroll
    for (int i = 0; i < 4; i++) {
        uint4 u = *(uint4*)(p + i * 8);
        __nv_bfloat162* pr = (__nv_bfloat162*)&u;
        #pragma unroll
        for (int j = 0; j < 4; j++) {
            float2 f2 = __bfloat1622float2(pr[j]);
            int c = cb + i * 8 + j * 2;
            pr[j] = __floats2bfloat162_rn((f2.x - m) * inv * g_s[c] + b_s[c],
                                          (f2.y - m) * inv * g_s[c + 1] + b_s[c + 1]);
        }
        *(uint4*)(p + i * 8) = u;
    }
}

__global__ __launch_bounds__(256, 2) void fattn(
        const bf16* __restrict__ f1q, bf16* __restrict__ xo,
        const float* __restrict__ qg, const float* __restrict__ qb,
        const float* __restrict__ kg, const float* __restrict__ kb) {
    extern __shared__ __align__(16) bf16 fsm[];
    bf16* Qs = fsm;
    bf16* Ks = fsm + FA_TSZ;
    bf16* Vs = fsm + 3 * FA_TSZ;
    __shared__ float qg_s[64], qb_s[64], kg_s[64], kb_s[64];

    const int t = threadIdx.x;
    const int lane = t & 31, w = t >> 5;
    const int bh = blockIdx.y;
    const int q0 = blockIdx.x * 128;
    const int b = bh / HEADS, h = bh % HEADS;
    const bf16* rowbase = f1q + (size_t)(b * SEQ) * QKVN;
    const bf16* qp = rowbase + (size_t)q0 * QKVN + h * HD;
    const bf16* kp = rowbase + DIMC + h * HD;
    const bf16* vp = rowbase + 2 * DIMC + h * HD;

    if (t < 64) {
        qg_s[t] = qg[t] * 0.125f; qb_s[t] = qb[t] * 0.125f;
        kg_s[t] = kg[t];          kb_s[t] = kb[t];
    }

    fa_load_tile(qp, Qs, t, QKVN);
    cp_commit();
    fa_load_tile(kp, Ks, t, QKVN);
    fa_load_tile(vp, Vs, t, QKVN);
    cp_commit();

    cp_wait1();
    __syncthreads();
    fa_ln_tile(Qs, qg_s, qb_s, t);
    __syncthreads();
    uint32_t qf[4][4];
    #pragma unroll
    for (int kk = 0; kk < 4; kk++) {
        uint32_t a = smem_u32(Qs + (w * 16 + (lane & 15)) * FA_LDS + kk * 16 + (lane >> 4) * 8);
        ldm_x4(qf[kk][0], qf[kk][1], qf[kk][2], qf[kk][3], a);
    }

    float oacc[8][4];
    #pragma unroll
    for (int jn = 0; jn < 8; jn++)
        #pragma unroll
        for (int e = 0; e < 4; e++) oacc[jn][e] = 0.f;
    float m0r = -1e30f, m1r = -1e30f, l0 = 0.f, l1 = 0.f;

    for (int c = 0; c < SEQ / 128; c++) {
        cp_wait0();                 /* K/V chunk c resident */
        __syncthreads();            /* all warps done with the other buffer */
        if (c + 1 < SEQ / 128) {
            int sn = (c + 1) & 1;
            fa_load_tile(kp + (size_t)(c + 1) * 128 * QKVN, Ks + sn * FA_TSZ, t, QKVN);
            fa_load_tile(vp + (size_t)(c + 1) * 128 * QKVN, Vs + sn * FA_TSZ, t, QKVN);
        }
        cp_commit();

        const int s = c & 1;
        bf16* ks = Ks + s * FA_TSZ;
        bf16* vs = Vs + s * FA_TSZ;

        fa_ln_tile(ks, kg_s, kb_s, t);
        __syncthreads();

        #pragma unroll
        for (int half = 0; half < 2; half++) {
            bf16* ksh = ks + half * 64 * FA_LDS;
            bf16* vsh = vs + half * 64 * FA_LDS;

            float sacc[8][4];
            #pragma unroll
            for (int j = 0; j < 8; j++)
                #pragma unroll
                for (int e = 0; e < 4; e++) sacc[j][e] = 0.f;
            #pragma unroll
            for (int kk = 0; kk < 4; kk++) {
                #pragma unroll
                for (int j2 = 0; j2 < 4; j2++) {
                    uint32_t r0, r1, r2, r3;
                    uint32_t a = smem_u32(ksh + (j2 * 16 + (lane >> 4) * 8 + (lane & 7)) * FA_LDS
                                          + kk * 16 + ((lane >> 3) & 1) * 8);
                    ldm_x4(r0, r1, r2, r3, a);
                    uint32_t bb0[2] = {r0, r1};
                    uint32_t bb1[2] = {r2, r3};
                    mma16816(sacc[2 * j2],     qf[kk], bb0);
                    mma16816(sacc[2 * j2 + 1], qf[kk], bb1);
                }
            }

            float mx0 = -1e30f, mx1 = -1e30f;
            #pragma unroll
            for (int j = 0; j < 8; j++) {
                mx0 = fmaxf(mx0, fmaxf(sacc[j][0], sacc[j][1]));
                mx1 = fmaxf(mx1, fmaxf(sacc[j][2], sacc[j][3]));
            }
            mx0 = fmaxf(mx0, __shfl_xor_sync(0xffffffffu, mx0, 1));
            mx0 = fmaxf(mx0, __shfl_xor_sync(0xffffffffu, mx0, 2));
            mx1 = fmaxf(mx1, __shfl_xor_sync(0xffffffffu, mx1, 1));
            mx1 = fmaxf(mx1, __shfl_xor_sync(0xffffffffu, mx1, 2));
            float mn0 = fmaxf(m0r, mx0), mn1 = fmaxf(m1r, mx1);
            float al0 = __expf(m0r - mn0), al1 = __expf(m1r - mn1);
            m0r = mn0; m1r = mn1;

            float sum0 = 0.f, sum1 = 0.f;
            #pragma unroll
            for (int j = 0; j < 8; j++) {
                sacc[j][0] = __expf(sacc[j][0] - mn0);
                sacc[j][1] = __expf(sacc[j][1] - mn0);
                sacc[j][2] = __expf(sacc[j][2] - mn1);
                sacc[j][3] = __expf(sacc[j][3] - mn1);
                sum0 += sacc[j][0] + sacc[j][1];
                sum1 += sacc[j][2] + sacc[j][3];
            }
            sum0 += __shfl_xor_sync(0xffffffffu, sum0, 1);
            sum0 += __shfl_xor_sync(0xffffffffu, sum0, 2);
            sum1 += __shfl_xor_sync(0xffffffffu, sum1, 1);
            sum1 += __shfl_xor_sync(0xffffffffu, sum1, 2);
            l0 = l0 * al0 + sum0;
            l1 = l1 * al1 + sum1;
            #pragma unroll
            for (int jn = 0; jn < 8; jn++) {
                oacc[jn][0] *= al0; oacc[jn][1] *= al0;
                oacc[jn][2] *= al1; oacc[jn][3] *= al1;
            }

            uint32_t pa[4][4];
            #pragma unroll
            for (int jp = 0; jp < 4; jp++) {
                pa[jp][0] = packbf2(sacc[2 * jp][0],     sacc[2 * jp][1]);
                pa[jp][1] = packbf2(sacc[2 * jp][2],     sacc[2 * jp][3]);
                pa[jp][2] = packbf2(sacc[2 * jp + 1][0], sacc[2 * jp + 1][1]);
                pa[jp][3] = packbf2(sacc[2 * jp + 1][2], sacc[2 * jp + 1][3]);
            }
            #pragma unroll
            for (int jp = 0; jp < 4; jp++) {
                #pragma unroll
                for (int j2 = 0; j2 < 4; j2++) {
                    uint32_t r0, r1, r2, r3;
                    uint32_t a = smem_u32(vsh + (jp * 16 + (lane & 15)) * FA_LDS
                                          + (j2 * 2 + (lane >> 4)) * 8);
                    ldm_x4_t(r0, r1, r2, r3, a);
                    uint32_t bb0[2] = {r0, r1};
                    uint32_t bb1[2] = {r2, r3};
                    mma16816(oacc[2 * j2],     pa[jp], bb0);
                    mma16816(oacc[2 * j2 + 1], pa[jp], bb1);
                }
            }
        }
    }

    float inv0 = 1.f / l0, inv1 = 1.f / l1;
    int rA = lane >> 2;
    int tok0 = b * SEQ + q0 + w * 16 + rA;
    int colb = h * HD + (lane & 3) * 2;
    #pragma unroll
    for (int jn = 0; jn < 8; jn++) {
        __nv_bfloat162 v0 = __floats2bfloat162_rn(oacc[jn][0] * inv0, oacc[jn][1] * inv0);
        __nv_bfloat162 v1 = __floats2bfloat162_rn(oacc[jn][2] * inv1, oacc[jn][3] * inv1);
        *(__nv_bfloat162*)(xo + (size_t)tok0 * DIMC + colb + jn * 8) = v0;
        *(__nv_bfloat162*)(xo + (size_t)(tok0 + 8) * DIMC + colb + jn * 8) = v1;
    }
}

/* ---------------- reductions ------------------------------------------------ */
__device__ __forceinline__ float blockReduceSum(float val) {
    __shared__ float sh[32];
    int lane = threadIdx.x & 31, wid = threadIdx.x >> 5;
    #pragma unroll
    for (int o = 16; o > 0; o >>= 1) val += __shfl_down_sync(0xffffffffu, val, o);
    if (lane == 0) sh[wid] = val;
    __syncthreads();
    val = (threadIdx.x < (blockDim.x >> 5)) ? sh[threadIdx.x] : 0.f;
    if (wid == 0) {
        #pragma unroll
        for (int o = 16; o > 0; o >>= 1) val += __shfl_down_sync(0xffffffffu, val, o);
        if (lane == 0) sh[0] = val;
    }
    __syncthreads();
    float r = sh[0];
    __syncthreads();
    return r;
}

/* ---------------- LayerNorm -> bf16 ---------------------------------------- */
__global__ void ln_rows(const float* __restrict__ x, const float* __restrict__ g,
                        const float* __restrict__ b, bf16* __restrict__ outb) {
    int row = blockIdx.x, t = threadIdx.x;
    const float* xr = x + (size_t)row * DIMC;
    float v[4]; float s = 0.f;
    #pragma unroll
    for (int i = 0; i < 4; i++) { v[i] = xr[i * 256 + t]; s += v[i]; }
    float mean = blockReduceSum(s) * (1.f / DIMC);
    float s2 = 0.f;
    #pragma unroll
    for (int i = 0; i < 4; i++) { float d = v[i] - mean; s2 += d * d; }
    float inv = rsqrtf(blockReduceSum(s2) * (1.f / DIMC) + 1e-5f);
    bf16* orow = outb + (size_t)row * DIMC;
    #pragma unroll
    for (int i = 0; i < 4; i++) {
        int c = i * 256 + t;
        orow[c] = __float2bfloat16((v[i] - mean) * inv * g[c] + b[c]);
    }
}

/* ---------------- all four weight conversions in one launch ----------------- */
__global__ void convert_all(const float* __restrict__ W1, const float* __restrict__ projW,
                            const float* __restrict__ mlpW, const float* __restrict__ W2,
                            bf16* __restrict__ d1, bf16* __restrict__ d2,
                            bf16* __restrict__ d3, bf16* __restrict__ d4) {
    int z = blockIdx.y;
    const float* src; bf16* dst; int srows, scols, dcols; long long total;
    if (z == 0)      { src = W1;    dst = d1; srows = DIMC;   scols = F1N;  dcols = F1NP; total = (long long)DIMC * F1NP; }
    else if (z == 1) { src = projW; dst = d2; srows = DIMC;   scols = DIMC; dcols = DIMC; total = (long long)DIMC * DIMC; }
    else if (z == 2) { src = mlpW;  dst = d3; srows = MLPH;   scols = DIMC; dcols = DIMC; total = (long long)MLPKP * DIMC; }
    else             { src = W2;    dst = d4; srows = 2*DIMC; scols = DIMC; dcols = DIMC; total = (long long)2 * DIMC * DIMC; }
    long long i = (long long)blockIdx.x * 256 + threadIdx.x;
    if (i >= total) return;
    int r = (int)(i / dcols), c = (int)(i % dcols);
    float v = (r < srows && c < scols) ? src[(size_t)r * scols + c] : 0.f;
    dst[i] = __float2bfloat16(v);
}

/* ---------------- launcher -------------------------------------------------- */
extern "C" void kernel_launch(void* const* d_in, const int* in_sizes, int n_in,
                              void* d_out, int out_size) {
    const float* x      = (const float*)d_in[0];
    const float* norm_g = (const float*)d_in[1];
    const float* norm_b = (const float*)d_in[2];
    const float* W1     = (const float*)d_in[3];
    const float* b1     = (const float*)d_in[4];
    const float* qn_g   = (const float*)d_in[5];
    const float* qn_b   = (const float*)d_in[6];
    const float* kn_g   = (const float*)d_in[7];
    const float* kn_b   = (const float*)d_in[8];
    const float* projW  = (const float*)d_in[9];
    const float* projb  = (const float*)d_in[10];
    const float* mlpW   = (const float*)d_in[11];
    const float* W2     = (const float*)d_in[12];
    const float* b2     = (const float*)d_in[13];
    const float* ls_g   = (const float*)d_in[14];
    float* out = (float*)d_out;

    unsigned char* base = 0;
    cudaGetSymbolAddress((void**)&base, g_scratch);

    bf16*  p_normx = (bf16*)(base + OF_NORMX);
    bf16*  p_W1b   = (bf16*)(base + OF_W1B);
    bf16*  p_projWb= (bf16*)(base + OF_PROJW);
    bf16*  p_mlpWb = (bf16*)(base + OF_MLPW);
    bf16*  p_W2b   = (bf16*)(base + OF_W2B);
    bf16*  p_f1q   = (bf16*)(base + OF_F1Q);
    bf16*  p_xo    = (bf16*)(base + OF_XO);
    bf16*  p_gelu  = (bf16*)(base + OF_GELU);
    bf16*  p_comb  = (bf16*)(base + OF_COMB);

    static int attr_done = 0;
    static cudaStream_t s2;
    static cudaEvent_t ev0, ev1, ev2, ev3;
    if (!attr_done) {
        cudaFuncSetAttribute(hgemm<1>, cudaFuncAttributeMaxDynamicSharedMemorySize, HG_SMEM);
        cudaFuncSetAttribute(hgemm<2>, cudaFuncAttributeMaxDynamicSharedMemorySize, HG_SMEM);
        cudaFuncSetAttribute(hgemm<3>, cudaFuncAttributeMaxDynamicSharedMemorySize, HG_SMEM);
        cudaFuncSetAttribute(fattn,    cudaFuncAttributeMaxDynamicSharedMemorySize, FA_SMEM);
        cudaStreamCreateWithFlags(&s2, cudaStreamNonBlocking);
        cudaEventCreateWithFlags(&ev0, cudaEventDisableTiming);
        cudaEventCreateWithFlags(&ev1, cudaEventDisableTiming);
        cudaEventCreateWithFlags(&ev2, cudaEventDisableTiming);
        cudaEventCreateWithFlags(&ev3, cudaEventDisableTiming);
        attr_done = 1;
    }

    /* fork: weight conversion on s2 alongside ln_rows on stream 0 */
    cudaEventRecord(ev0, 0);
    cudaStreamWaitEvent(s2, ev0, 0);
    convert_all<<<dim3((unsigned)(((long long)DIMC * F1NP + 255) / 256), 4), 256, 0, s2>>>(
        W1, projW, mlpW, W2, p_W1b, p_projWb, p_mlpWb, p_W2b);
    cudaEventRecord(ev1, s2);

    ln_rows<<<TOK, 256>>>(x, norm_g, norm_b, p_normx);
    cudaStreamWaitEvent(0, ev1, 0);

    /* f1 = normx @ W1 + b1 : qkv -> f1q bf16, gelu -> p_gelu bf16 */
    hgemm<3><<<dim3(F1NP / 128, TOK / 128), 256, HG_SMEM>>>(
        p_normx, p_W1b, p_f1q, p_gelu, DIMC, DIMC, F1NP, 0, b1, F1N, 0, 0);

    /* fork: mlp GEMM (only needs gelu) runs concurrently with fattn */
    cudaEventRecord(ev2, 0);
    cudaStreamWaitEvent(s2, ev2, 0);
    hgemm<1><<<dim3(DIMC / 128, TOK / 128), 256, HG_SMEM, s2>>>(
        p_gelu, p_mlpWb, p_comb + DIMC, 0, MLPKP, MLPKP, DIMC, 2 * DIMC, 0, 0, 0, 0);
    cudaEventRecord(ev3, s2);

    /* attention (stream 0) */
    fattn<<<dim3(SEQ / 128, BH), 256, FA_SMEM>>>(p_f1q, p_xo, qn_g, qn_b, kn_g, kn_b);

    /* proj GEMM (stream 0, after fattn) */
    hgemm<1><<<dim3(DIMC / 128, TOK / 128), 256, HG_SMEM>>>(
        p_xo, p_projWb, p_comb, 0, DIMC, DIMC, DIMC, 2 * DIMC, projb, DIMC, 0, 0);

    /* join: W2 needs both halves of comb */
    cudaStreamWaitEvent(0, ev3, 0);
    hgemm<2><<<dim3(DIMC / 128, TOK / 128), 256, HG_SMEM>>>(
        p_comb, p_W2b, out, 0, 2 * DIMC, 2 * DIMC, DIMC, DIMC, b2, DIMC, x, ls_g);
}